// round 1
// baseline (speedup 1.0000x reference)
#include <cuda_runtime.h>
#include <cuda_bf16.h>
#include <cstdint>

// ---------------- problem constants ----------------
#define B_   2
#define S_   2048
#define HID_ 2048
#define H_   16
#define QL_  1536
#define KVL_ 512
#define DN_  128
#define DR_  64
#define DV_  128
#define DQK_ 192
#define NT_  (B_*S_)        // 4096 tokens

// ---------------- scratch (static device globals; no alloc) ----------------
__device__ float g_qan[(size_t)NT_ * QL_];          // q after lora-A + rmsnorm
__device__ float g_q[(size_t)NT_ * (H_ * DQK_)];    // q after lora-B (+rope)
__device__ float g_kvall[(size_t)NT_ * (KVL_ + DR_)]; // kv_a output (kv_lat | k_pe)
__device__ float g_kv[(size_t)NT_ * (H_ * (DN_ + DV_))]; // kv after lora-B
__device__ float g_attn[(size_t)NT_ * (H_ * DV_)];  // attention output

// ---------------- generic SGEMM: C[M,N] = A[M,K] @ W[N,K]^T ----------------
#define BM 128
#define BN 128
#define BKK 16

__global__ __launch_bounds__(256) void gemm_atb(
    const float* __restrict__ A, int lda,
    const float* __restrict__ W, int ldw,
    float* __restrict__ C, int ldc,
    int M, int N, int K)
{
    __shared__ float As[BKK][BM];
    __shared__ float Ws[BKK][BN + 4];

    const int tid = threadIdx.x;
    const int bm = blockIdx.y * BM;
    const int bn = blockIdx.x * BN;
    const int tx = tid & 15;
    const int ty = tid >> 4;

    float acc[8][8];
#pragma unroll
    for (int i = 0; i < 8; i++)
#pragma unroll
        for (int j = 0; j < 8; j++) acc[i][j] = 0.f;

    for (int k0 = 0; k0 < K; k0 += BKK) {
        // load A tile (128x16) as float4, store transposed
#pragma unroll
        for (int l = 0; l < 2; l++) {
            int idx = tid + l * 256;          // 0..511
            int m = idx >> 2;
            int kq = (idx & 3) << 2;
            float4 v = *reinterpret_cast<const float4*>(
                &A[(size_t)(bm + m) * lda + k0 + kq]);
            As[kq + 0][m] = v.x; As[kq + 1][m] = v.y;
            As[kq + 2][m] = v.z; As[kq + 3][m] = v.w;
        }
        // load W tile (128x16) as float4, store transposed (bounds-guarded on N)
#pragma unroll
        for (int l = 0; l < 2; l++) {
            int idx = tid + l * 256;
            int n = idx >> 2;
            int kq = (idx & 3) << 2;
            float4 v = make_float4(0.f, 0.f, 0.f, 0.f);
            if (bn + n < N)
                v = *reinterpret_cast<const float4*>(
                    &W[(size_t)(bn + n) * ldw + k0 + kq]);
            Ws[kq + 0][n] = v.x; Ws[kq + 1][n] = v.y;
            Ws[kq + 2][n] = v.z; Ws[kq + 3][n] = v.w;
        }
        __syncthreads();
#pragma unroll
        for (int k = 0; k < BKK; k++) {
            float ra[8], rb[8];
#pragma unroll
            for (int i = 0; i < 8; i++) ra[i] = As[k][ty * 8 + i];
#pragma unroll
            for (int j = 0; j < 8; j++) rb[j] = Ws[k][tx * 8 + j];
#pragma unroll
            for (int i = 0; i < 8; i++)
#pragma unroll
                for (int j = 0; j < 8; j++)
                    acc[i][j] = fmaf(ra[i], rb[j], acc[i][j]);
        }
        __syncthreads();
    }
#pragma unroll
    for (int i = 0; i < 8; i++) {
        int m = bm + ty * 8 + i;
#pragma unroll
        for (int j = 0; j < 8; j++) {
            int n = bn + tx * 8 + j;
            if (n < N) C[(size_t)m * ldc + n] = acc[i][j];
        }
    }
}

// ---------------- RMSNorm (in-place, one block per row) ----------------
__global__ void rmsnorm_kernel(float* __restrict__ x, const float* __restrict__ w,
                               int n, int stride)
{
    const int row = blockIdx.x;
    float* p = x + (size_t)row * stride;
    __shared__ float red[256];
    float s = 0.f;
    for (int i = threadIdx.x; i < n; i += 256) { float v = p[i]; s += v * v; }
    red[threadIdx.x] = s;
    __syncthreads();
    for (int o = 128; o > 0; o >>= 1) {
        if (threadIdx.x < o) red[threadIdx.x] += red[threadIdx.x + o];
        __syncthreads();
    }
    float inv = rsqrtf(red[0] / n + 1e-6f);
    for (int i = threadIdx.x; i < n; i += 256) p[i] = p[i] * inv * w[i];
}

// ---------------- RoPE ----------------
// q: [NT, H*192], rope on q[..., h*192+128 .. h*192+191]
__global__ void rope_q_kernel(float* __restrict__ q, const float* __restrict__ fc)
{
    const int t = blockIdx.x;    // token
    const int h = blockIdx.y;    // head
    const int i = threadIdx.x;   // 0..31 (pair index)
    const int s = t & (S_ - 1);
    const float c  = fc[(s * 32 + i) * 2 + 0];
    const float sn = fc[(s * 32 + i) * 2 + 1];
    float* base = q + (size_t)t * (H_ * DQK_) + h * DQK_ + DN_;
    float xr = base[2 * i], xi = base[2 * i + 1];
    base[2 * i]     = xr * c - xi * sn;
    base[2 * i + 1] = xr * sn + xi * c;
}

// k_pe: g_kvall[t, 512..575]
__global__ void rope_k_kernel(float* __restrict__ kva, const float* __restrict__ fc)
{
    const int t = blockIdx.x;
    const int i = threadIdx.x;
    const int s = t & (S_ - 1);
    const float c  = fc[(s * 32 + i) * 2 + 0];
    const float sn = fc[(s * 32 + i) * 2 + 1];
    float* base = kva + (size_t)t * (KVL_ + DR_) + KVL_;
    float xr = base[2 * i], xi = base[2 * i + 1];
    base[2 * i]     = xr * c - xi * sn;
    base[2 * i + 1] = xr * sn + xi * c;
}

// ---------------- flash attention (fp32, online softmax) ----------------
#define BQ  64
#define BKT 64
#define QSS 196   // padded stride for 192-wide rows
#define VSS 132   // padded stride for 128-wide rows
#define SSS 65

// smem float offsets
#define OFF_QS   0
#define OFF_KS   (BQ * QSS)                 // 12544
#define OFF_VS   (OFF_KS + BKT * QSS)       // 25088
#define OFF_SS   (OFF_VS + BKT * VSS)       // 33536
#define OFF_CORR (OFF_SS + BQ * SSS)        // 37696
#define OFF_LINV (OFF_CORR + BQ)            // 37760
#define SMEM_FLOATS (OFF_LINV + BQ)         // 37824
#define SMEM_BYTES (SMEM_FLOATS * 4)        // 151296

extern __shared__ float smem[];

__global__ __launch_bounds__(256) void attn_kernel(
    const float* __restrict__ gq,     // [NT, H*192]
    const float* __restrict__ gkv,    // [NT, H*256]  (k_nope | v)
    const float* __restrict__ gkvall, // [NT, 576]    (k_pe at 512..575)
    float* __restrict__ gout)         // [NT, H*128]
{
    const int qt = blockIdx.x;
    const int h  = blockIdx.y;
    const int b  = blockIdx.z;
    const int tid = threadIdx.x;
    const int q0 = qt * BQ;

    float* Qs = smem + OFF_QS;
    float* Ks = smem + OFF_KS;
    float* Vs = smem + OFF_VS;
    float* Ss = smem + OFF_SS;
    float* corr_s = smem + OFF_CORR;
    float* linv_s = smem + OFF_LINV;

    const float scale = rsqrtf((float)DQK_);

    // load Q tile, pre-scaled
    for (int idx = tid; idx < BQ * DQK_; idx += 256) {
        int qi = idx / DQK_, d = idx % DQK_;
        int t = b * S_ + q0 + qi;
        Qs[qi * QSS + d] = gq[(size_t)t * (H_ * DQK_) + h * DQK_ + d] * scale;
    }

    const int qi_own = tid & 63;
    const int hd = tid >> 6;       // 0..3
    const int d0 = hd * 32;

    float m = -1e30f, l = 0.f;
    float acc[32];
#pragma unroll
    for (int j = 0; j < 32; j++) acc[j] = 0.f;

    const int qb = tid >> 4;       // 0..15
    const int kb = tid & 15;       // 0..15

    const int ntiles = q0 / BKT + 1;
    for (int kt = 0; kt < ntiles; kt++) {
        const int k0 = kt * BKT;
        // load K tile (nope from gkv, rope from gkvall) and V tile
        for (int idx = tid; idx < BKT * DQK_; idx += 256) {
            int kj = idx / DQK_, d = idx % DQK_;
            int t = b * S_ + k0 + kj;
            float v;
            if (d < DN_) v = gkv[(size_t)t * (H_ * 256) + h * 256 + d];
            else         v = gkvall[(size_t)t * (KVL_ + DR_) + KVL_ + (d - DN_)];
            Ks[kj * QSS + d] = v;
        }
        for (int idx = tid; idx < BKT * DV_; idx += 256) {
            int kj = idx / DV_, d = idx % DV_;
            int t = b * S_ + k0 + kj;
            Vs[kj * VSS + d] = gkv[(size_t)t * (H_ * 256) + h * 256 + DN_ + d];
        }
        __syncthreads();

        // scores: each thread computes 4x4 block, float4 over d
        float sc[4][4];
#pragma unroll
        for (int i = 0; i < 4; i++)
#pragma unroll
            for (int j = 0; j < 4; j++) sc[i][j] = 0.f;

        const float* qp = &Qs[(qb * 4) * QSS];
        const float* kp = &Ks[(kb * 4) * QSS];
        for (int d = 0; d < DQK_; d += 4) {
            float4 ra[4], rb[4];
#pragma unroll
            for (int i = 0; i < 4; i++)
                ra[i] = *reinterpret_cast<const float4*>(&qp[i * QSS + d]);
#pragma unroll
            for (int j = 0; j < 4; j++)
                rb[j] = *reinterpret_cast<const float4*>(&kp[j * QSS + d]);
#pragma unroll
            for (int i = 0; i < 4; i++)
#pragma unroll
                for (int j = 0; j < 4; j++) {
                    sc[i][j] = fmaf(ra[i].x, rb[j].x, sc[i][j]);
                    sc[i][j] = fmaf(ra[i].y, rb[j].y, sc[i][j]);
                    sc[i][j] = fmaf(ra[i].z, rb[j].z, sc[i][j]);
                    sc[i][j] = fmaf(ra[i].w, rb[j].w, sc[i][j]);
                }
        }
#pragma unroll
        for (int i = 0; i < 4; i++)
#pragma unroll
            for (int j = 0; j < 4; j++) {
                int qg = q0 + qb * 4 + i;
                int kg = k0 + kb * 4 + j;
                Ss[(qb * 4 + i) * SSS + kb * 4 + j] =
                    (kg <= qg) ? sc[i][j] : -1e30f;
            }
        __syncthreads();

        // online softmax: hd==0 threads own full rows; write p back into Ss
        if (hd == 0) {
            float mnew = m;
            for (int kj = 0; kj < BKT; kj++)
                mnew = fmaxf(mnew, Ss[qi_own * SSS + kj]);
            float c = __expf(m - mnew);
            float ls = 0.f;
            for (int kj = 0; kj < BKT; kj++) {
                float p = __expf(Ss[qi_own * SSS + kj] - mnew);
                Ss[qi_own * SSS + kj] = p;
                ls += p;
            }
            l = l * c + ls;
            m = mnew;
            corr_s[qi_own] = c;
        }
        __syncthreads();

        // accumulate: acc = acc*corr + P @ V (thread owns 32 d-columns of one query)
        {
            float c = corr_s[qi_own];
#pragma unroll
            for (int j = 0; j < 32; j++) acc[j] *= c;
            for (int kj = 0; kj < BKT; kj++) {
                float p = Ss[qi_own * SSS + kj];
                const float4* vp =
                    reinterpret_cast<const float4*>(&Vs[kj * VSS + d0]);
#pragma unroll
                for (int j4 = 0; j4 < 8; j4++) {
                    float4 v = vp[j4];
                    acc[j4 * 4 + 0] = fmaf(p, v.x, acc[j4 * 4 + 0]);
                    acc[j4 * 4 + 1] = fmaf(p, v.y, acc[j4 * 4 + 1]);
                    acc[j4 * 4 + 2] = fmaf(p, v.z, acc[j4 * 4 + 2]);
                    acc[j4 * 4 + 3] = fmaf(p, v.w, acc[j4 * 4 + 3]);
                }
            }
        }
        __syncthreads();
    }

    if (hd == 0) linv_s[qi_own] = 1.f / l;
    __syncthreads();
    const float li = linv_s[qi_own];
    const int t = b * S_ + q0 + qi_own;
    float* outp = &gout[(size_t)t * (H_ * DV_) + h * DV_ + d0];
#pragma unroll
    for (int j = 0; j < 32; j++) outp[j] = acc[j] * li;
}

// ---------------- launcher ----------------
extern "C" void kernel_launch(void* const* d_in, const int* in_sizes, int n_in,
                              void* d_out, int out_size)
{
    const float* x       = (const float*)d_in[0];  // [B,S,HID]
    const float* freqs   = (const float*)d_in[1];  // [S,32,2]
    const float* wq_a    = (const float*)d_in[2];  // [1536,2048]
    const float* q_an_w  = (const float*)d_in[3];  // [1536]
    const float* wq_b    = (const float*)d_in[4];  // [3072,1536]
    const float* wkv_a   = (const float*)d_in[5];  // [576,2048]
    const float* kv_n_w  = (const float*)d_in[6];  // [512]
    const float* wkv_b   = (const float*)d_in[7];  // [4096,512]
    const float* wo      = (const float*)d_in[8];  // [2048,2048]
    float* out = (float*)d_out;

    float *qan, *q, *kvall, *kv, *attn;
    cudaGetSymbolAddress((void**)&qan,   g_qan);
    cudaGetSymbolAddress((void**)&q,     g_q);
    cudaGetSymbolAddress((void**)&kvall, g_kvall);
    cudaGetSymbolAddress((void**)&kv,    g_kv);
    cudaGetSymbolAddress((void**)&attn,  g_attn);

    cudaFuncSetAttribute(attn_kernel,
                         cudaFuncAttributeMaxDynamicSharedMemorySize, SMEM_BYTES);

    // 1. q_a = x @ wq_a^T : [4096,1536]
    gemm_atb<<<dim3(QL_ / BN, NT_ / BM), 256>>>(
        x, HID_, wq_a, HID_, qan, QL_, NT_, QL_, HID_);
    // 2. rmsnorm(q_a)
    rmsnorm_kernel<<<NT_, 256>>>(qan, q_an_w, QL_, QL_);
    // 3. q = q_a_n @ wq_b^T : [4096,3072]
    gemm_atb<<<dim3((H_ * DQK_) / BN, NT_ / BM), 256>>>(
        qan, QL_, wq_b, QL_, q, H_ * DQK_, NT_, H_ * DQK_, QL_);
    // 4. rope on q_pe
    rope_q_kernel<<<dim3(NT_, H_), 32>>>(q, freqs);
    // 5. kv_all = x @ wkv_a^T : [4096,576]
    gemm_atb<<<dim3((KVL_ + DR_ + BN - 1) / BN, NT_ / BM), 256>>>(
        x, HID_, wkv_a, HID_, kvall, KVL_ + DR_, NT_, KVL_ + DR_, HID_);
    // 6. rope on k_pe, rmsnorm on kv_lat (disjoint regions)
    rope_k_kernel<<<NT_, 32>>>(kvall, freqs);
    rmsnorm_kernel<<<NT_, 256>>>(kvall, kv_n_w, KVL_, KVL_ + DR_);
    // 7. kv = kvn @ wkv_b^T : [4096,4096]
    gemm_atb<<<dim3((H_ * 256) / BN, NT_ / BM), 256>>>(
        kvall, KVL_ + DR_, wkv_b, KVL_, kv, H_ * 256, NT_, H_ * 256, KVL_);
    // 8. attention
    attn_kernel<<<dim3(S_ / BQ, H_, B_), 256, SMEM_BYTES>>>(q, kv, kvall, attn);
    // 9. out = attn @ wo^T : [4096,2048]
    gemm_atb<<<dim3(HID_ / BN, NT_ / BM), 256>>>(
        attn, H_ * DV_, wo, HID_, out, HID_, NT_, HID_, H_ * DV_);
}

// round 3
// speedup vs baseline: 1.3519x; 1.3519x over previous
#include <cuda_runtime.h>
#include <cuda_bf16.h>
#include <cstdint>

// ---------------- problem constants ----------------
#define B_   2
#define S_   2048
#define HID_ 2048
#define H_   16
#define QL_  1536
#define KVL_ 512
#define DN_  128
#define DR_  64
#define DV_  128
#define DQK_ 192
#define NT_  (B_*S_)        // 4096 tokens

typedef __nv_bfloat16 bf16;

// ---------------- scratch (static device globals; no alloc) ----------------
__device__ __align__(128) float g_qan[(size_t)NT_ * QL_];
__device__ __align__(128) float g_q[(size_t)NT_ * (H_ * DQK_)];
__device__ __align__(128) float g_kvall[(size_t)NT_ * (KVL_ + DR_)];
__device__ __align__(128) float g_kv[(size_t)NT_ * (H_ * (DN_ + DV_))];
__device__ __align__(128) float g_attn[(size_t)NT_ * (H_ * DV_)];

__device__ __align__(128) bf16 g_xhi[(size_t)NT_ * HID_],  g_xlo[(size_t)NT_ * HID_];
__device__ __align__(128) bf16 g_qanhi[(size_t)NT_ * QL_], g_qanlo[(size_t)NT_ * QL_];
__device__ __align__(128) bf16 g_kvnhi[(size_t)NT_ * KVL_],g_kvnlo[(size_t)NT_ * KVL_];
__device__ __align__(128) bf16 g_athi[(size_t)NT_ * (H_*DV_)], g_atlo[(size_t)NT_ * (H_*DV_)];
__device__ __align__(128) bf16 g_wqahi[(size_t)QL_ * HID_],        g_wqalo[(size_t)QL_ * HID_];
__device__ __align__(128) bf16 g_wqbhi[(size_t)(H_*DQK_) * QL_],   g_wqblo[(size_t)(H_*DQK_) * QL_];
__device__ __align__(128) bf16 g_wkvahi[(size_t)(KVL_+DR_) * HID_],g_wkvalo[(size_t)(KVL_+DR_) * HID_];
__device__ __align__(128) bf16 g_wkvbhi[(size_t)(H_*256) * KVL_],  g_wkvblo[(size_t)(H_*256) * KVL_];
__device__ __align__(128) bf16 g_wohi[(size_t)HID_ * (H_*DV_)],    g_wolo[(size_t)HID_ * (H_*DV_)];

// ================= PTX helpers (baseline compute_103 features only) =========
__device__ __forceinline__ uint32_t smem_u32(const void* p) {
    uint32_t a;
    asm("{ .reg .u64 t; cvta.to.shared.u64 t, %1; cvt.u32.u64 %0, t; }" : "=r"(a) : "l"(p));
    return a;
}
__device__ __forceinline__ void cp_async16(uint32_t dst, const void* src, int src_bytes) {
    asm volatile("cp.async.cg.shared.global [%0], [%1], 16, %2;"
                 :: "r"(dst), "l"(src), "r"(src_bytes) : "memory");
}
__device__ __forceinline__ void cp_commit() {
    asm volatile("cp.async.commit_group;" ::: "memory");
}
template <int N>
__device__ __forceinline__ void cp_wait() {
    asm volatile("cp.async.wait_group %0;" :: "n"(N) : "memory");
}
__device__ __forceinline__ void ldmx4(uint32_t* r, uint32_t addr) {
    asm volatile("ldmatrix.sync.aligned.m8n8.x4.shared.b16 {%0,%1,%2,%3}, [%4];"
                 : "=r"(r[0]), "=r"(r[1]), "=r"(r[2]), "=r"(r[3]) : "r"(addr));
}
__device__ __forceinline__ void mma16816(float* c, const uint32_t* a, uint32_t b0, uint32_t b1) {
    asm volatile(
        "mma.sync.aligned.m16n8k16.row.col.f32.bf16.bf16.f32 "
        "{%0,%1,%2,%3}, {%4,%5,%6,%7}, {%8,%9}, {%0,%1,%2,%3};"
        : "+f"(c[0]), "+f"(c[1]), "+f"(c[2]), "+f"(c[3])
        : "r"(a[0]), "r"(a[1]), "r"(a[2]), "r"(a[3]), "r"(b0), "r"(b1));
}

// ================= HMMA split-bf16 GEMM ======================================
// C[M,N] = (Ahi+Alo)[M,K] @ (Whi+Wlo)[N,K]^T, fp32-grade via 3 bf16 products.
// BM=128 BN=128 BK=32, 256 threads (8 warps), warp tile 32x64.
#define GBK 32
#define ROWB 80                    // padded row pitch in bytes (32 bf16 + 8 pad)
#define PLANE (128 * ROWB)         // 10240 B
#define GBUF  (4 * PLANE)          // Ahi,Alo,Bhi,Blo = 40960 B
#define GSMEM (2 * GBUF)           // 81920 B

// load one 128x32 bf16 tile into padded smem (512 x 16B via cp.async)
__device__ __forceinline__ void load_tile(
    const bf16* __restrict__ g, int ld, int rowbase, int rowlim,
    int kcol, uint32_t sdst, int tid)
{
#pragma unroll
    for (int i = 0; i < 2; ++i) {
        int idx = tid + i * 256;          // 0..511
        int r = idx >> 2;
        int c8 = (idx & 3) << 3;
        int gr = rowbase + r;
        int ok = (gr < rowlim);
        const bf16* src = g + (size_t)(ok ? gr : rowbase) * ld + kcol + c8;
        cp_async16(sdst + r * ROWB + c8 * 2, src, ok ? 16 : 0);
    }
}

extern __shared__ uint8_t dsm[];

__global__ __launch_bounds__(256, 1) void gemm_hmma(
    const bf16* __restrict__ Ahi, const bf16* __restrict__ Alo,
    const bf16* __restrict__ Whi, const bf16* __restrict__ Wlo,
    float* __restrict__ C, int N, int K, int ldc)
{
    const int tid  = threadIdx.x;
    const int wid  = tid >> 5;
    const int lane = tid & 31;
    const int bm = blockIdx.y * 128;
    const int bn = blockIdx.x * 128;
    const int wm = (wid & 3) * 32;        // warp row offset in tile
    const int wn = (wid >> 2) * 64;       // warp col offset in tile
    const uint32_t sb = smem_u32(dsm);

    float acc[2][8][4];
#pragma unroll
    for (int i = 0; i < 2; i++)
#pragma unroll
        for (int j = 0; j < 8; j++)
#pragma unroll
            for (int k = 0; k < 4; k++) acc[i][j][k] = 0.f;

    const int nchunks = K / GBK;

    // prologue: chunk 0 -> buf 0
    {
        uint32_t buf = sb;
        load_tile(Ahi, K, bm, 1 << 30, 0, buf,             tid);
        load_tile(Alo, K, bm, 1 << 30, 0, buf + PLANE,     tid);
        load_tile(Whi, K, bn, N,       0, buf + 2 * PLANE, tid);
        load_tile(Wlo, K, bn, N,       0, buf + 3 * PLANE, tid);
        cp_commit();
    }

    // ldmatrix source addresses (fixed per thread, relative to buffer base)
    const uint32_t a_off = (uint32_t)((wm + (lane & 15)) * ROWB + ((lane >> 4) << 3) * 2);
    const uint32_t b_off = (uint32_t)((wn + (lane & 7)) * ROWB + ((lane >> 3) << 3) * 2);

    for (int c = 0; c < nchunks; ++c) {
        if (c + 1 < nchunks) {
            uint32_t buf = sb + ((c + 1) & 1) * GBUF;
            int kcol = (c + 1) * GBK;
            load_tile(Ahi, K, bm, 1 << 30, kcol, buf,             tid);
            load_tile(Alo, K, bm, 1 << 30, kcol, buf + PLANE,     tid);
            load_tile(Whi, K, bn, N,       kcol, buf + 2 * PLANE, tid);
            load_tile(Wlo, K, bn, N,       kcol, buf + 3 * PLANE, tid);
            cp_commit();
            cp_wait<1>();
        } else {
            cp_wait<0>();
        }
        __syncthreads();

        const uint32_t buf = sb + (c & 1) * GBUF;

        // A fragments: [plane][mi][kf][4]
        uint32_t afr[2][2][2][4];
#pragma unroll
        for (int pl = 0; pl < 2; ++pl)
#pragma unroll
            for (int mi = 0; mi < 2; ++mi)
#pragma unroll
                for (int kf = 0; kf < 2; ++kf)
                    ldmx4(afr[pl][mi][kf],
                          buf + pl * PLANE + a_off + mi * 16 * ROWB + kf * 32);

#pragma unroll
        for (int ni = 0; ni < 8; ++ni) {
            uint32_t bhi[4], blo[4];
            ldmx4(bhi, buf + 2 * PLANE + b_off + ni * 8 * ROWB);
            ldmx4(blo, buf + 3 * PLANE + b_off + ni * 8 * ROWB);
#pragma unroll
            for (int mi = 0; mi < 2; ++mi) {
                float* d = acc[mi][ni];
                mma16816(d, afr[0][mi][0], bhi[0], bhi[1]);   // hi*hi k0
                mma16816(d, afr[0][mi][1], bhi[2], bhi[3]);   // hi*hi k1
                mma16816(d, afr[0][mi][0], blo[0], blo[1]);   // hi*lo k0
                mma16816(d, afr[0][mi][1], blo[2], blo[3]);   // hi*lo k1
                mma16816(d, afr[1][mi][0], bhi[0], bhi[1]);   // lo*hi k0
                mma16816(d, afr[1][mi][1], bhi[2], bhi[3]);   // lo*hi k1
            }
        }
        __syncthreads();
    }

    // epilogue: direct float2 stores
    const int r0 = bm + wm + (lane >> 2);
    const int cb = bn + wn + (lane & 3) * 2;
#pragma unroll
    for (int mi = 0; mi < 2; ++mi)
#pragma unroll
        for (int ni = 0; ni < 8; ++ni) {
            int col = cb + ni * 8;
            if (col < N) {
                int row = r0 + mi * 16;
                *reinterpret_cast<float2*>(&C[(size_t)row * ldc + col]) =
                    make_float2(acc[mi][ni][0], acc[mi][ni][1]);
                *reinterpret_cast<float2*>(&C[(size_t)(row + 8) * ldc + col]) =
                    make_float2(acc[mi][ni][2], acc[mi][ni][3]);
            }
        }
}

// ================= converts =================
__global__ void convert_split(const float* __restrict__ src,
                              bf16* __restrict__ hi, bf16* __restrict__ lo, size_t n4)
{
    size_t i = (size_t)blockIdx.x * blockDim.x + threadIdx.x;
    if (i >= n4) return;
    float4 v = reinterpret_cast<const float4*>(src)[i];
    bf16 h0 = __float2bfloat16(v.x), h1 = __float2bfloat16(v.y);
    bf16 h2 = __float2bfloat16(v.z), h3 = __float2bfloat16(v.w);
    bf16 l0 = __float2bfloat16(v.x - __bfloat162float(h0));
    bf16 l1 = __float2bfloat16(v.y - __bfloat162float(h1));
    bf16 l2 = __float2bfloat16(v.z - __bfloat162float(h2));
    bf16 l3 = __float2bfloat16(v.w - __bfloat162float(h3));
    __nv_bfloat162* hp = reinterpret_cast<__nv_bfloat162*>(hi);
    __nv_bfloat162* lp = reinterpret_cast<__nv_bfloat162*>(lo);
    hp[2*i]   = __nv_bfloat162(h0, h1); hp[2*i+1] = __nv_bfloat162(h2, h3);
    lp[2*i]   = __nv_bfloat162(l0, l1); lp[2*i+1] = __nv_bfloat162(l2, l3);
}

__global__ void convert_split_kvn(const float* __restrict__ src,
                                  bf16* __restrict__ hi, bf16* __restrict__ lo)
{
    size_t i = (size_t)blockIdx.x * blockDim.x + threadIdx.x;
    if (i >= (size_t)NT_ * 128) return;
    size_t r = i >> 7, c4 = i & 127;
    float4 v = *reinterpret_cast<const float4*>(&src[r * (KVL_ + DR_) + c4 * 4]);
    bf16 h0 = __float2bfloat16(v.x), h1 = __float2bfloat16(v.y);
    bf16 h2 = __float2bfloat16(v.z), h3 = __float2bfloat16(v.w);
    bf16 l0 = __float2bfloat16(v.x - __bfloat162float(h0));
    bf16 l1 = __float2bfloat16(v.y - __bfloat162float(h1));
    bf16 l2 = __float2bfloat16(v.z - __bfloat162float(h2));
    bf16 l3 = __float2bfloat16(v.w - __bfloat162float(h3));
    size_t o = r * KVL_ + c4 * 4;
    __nv_bfloat162* hp = reinterpret_cast<__nv_bfloat162*>(&hi[o]);
    __nv_bfloat162* lp = reinterpret_cast<__nv_bfloat162*>(&lo[o]);
    hp[0] = __nv_bfloat162(h0, h1); hp[1] = __nv_bfloat162(h2, h3);
    lp[0] = __nv_bfloat162(l0, l1); lp[1] = __nv_bfloat162(l2, l3);
}

// ---------------- RMSNorm ----------------
__global__ void rmsnorm_kernel(float* __restrict__ x, const float* __restrict__ w,
                               int n, int stride)
{
    const int row = blockIdx.x;
    float* p = x + (size_t)row * stride;
    __shared__ float red[256];
    float s = 0.f;
    for (int i = threadIdx.x; i < n; i += 256) { float v = p[i]; s += v * v; }
    red[threadIdx.x] = s;
    __syncthreads();
    for (int o = 128; o > 0; o >>= 1) {
        if (threadIdx.x < o) red[threadIdx.x] += red[threadIdx.x + o];
        __syncthreads();
    }
    float inv = rsqrtf(red[0] / n + 1e-6f);
    for (int i = threadIdx.x; i < n; i += 256) p[i] = p[i] * inv * w[i];
}

// ---------------- RoPE ----------------
__global__ void rope_q_kernel(float* __restrict__ q, const float* __restrict__ fc)
{
    const int t = blockIdx.x, h = blockIdx.y, i = threadIdx.x;
    const int s = t & (S_ - 1);
    const float c  = fc[(s * 32 + i) * 2 + 0];
    const float sn = fc[(s * 32 + i) * 2 + 1];
    float* base = q + (size_t)t * (H_ * DQK_) + h * DQK_ + DN_;
    float xr = base[2 * i], xi = base[2 * i + 1];
    base[2 * i]     = xr * c - xi * sn;
    base[2 * i + 1] = xr * sn + xi * c;
}
__global__ void rope_k_kernel(float* __restrict__ kva, const float* __restrict__ fc)
{
    const int t = blockIdx.x, i = threadIdx.x;
    const int s = t & (S_ - 1);
    const float c  = fc[(s * 32 + i) * 2 + 0];
    const float sn = fc[(s * 32 + i) * 2 + 1];
    float* base = kva + (size_t)t * (KVL_ + DR_) + KVL_;
    float xr = base[2 * i], xi = base[2 * i + 1];
    base[2 * i]     = xr * c - xi * sn;
    base[2 * i + 1] = xr * sn + xi * c;
}

// ---------------- flash attention (fp32, online softmax) ----------------
#define BQ  64
#define BKT 64
#define QSS 196
#define VSS 132
#define SSS 65
#define OFF_QS   0
#define OFF_KS   (BQ * QSS)
#define OFF_VS   (OFF_KS + BKT * QSS)
#define OFF_SS   (OFF_VS + BKT * VSS)
#define OFF_CORR (OFF_SS + BQ * SSS)
#define OFF_LINV (OFF_CORR + BQ)
#define SMEM_FLOATS (OFF_LINV + BQ)
#define SMEM_BYTES (SMEM_FLOATS * 4)

__global__ __launch_bounds__(256) void attn_kernel(
    const float* __restrict__ gq, const float* __restrict__ gkv,
    const float* __restrict__ gkvall, float* __restrict__ gout)
{
    extern __shared__ float smem[];
    const int qt = blockIdx.x, h = blockIdx.y, b = blockIdx.z;
    const int tid = threadIdx.x;
    const int q0 = qt * BQ;

    float* Qs = smem + OFF_QS;
    float* Ks = smem + OFF_KS;
    float* Vs = smem + OFF_VS;
    float* Ss = smem + OFF_SS;
    float* corr_s = smem + OFF_CORR;
    float* linv_s = smem + OFF_LINV;

    const float scale = rsqrtf((float)DQK_);

    for (int idx = tid; idx < BQ * DQK_; idx += 256) {
        int qi = idx / DQK_, d = idx % DQK_;
        int t = b * S_ + q0 + qi;
        Qs[qi * QSS + d] = gq[(size_t)t * (H_ * DQK_) + h * DQK_ + d] * scale;
    }

    const int qi_own = tid & 63;
    const int hd = tid >> 6;
    const int d0 = hd * 32;

    float m = -1e30f, l = 0.f;
    float acc[32];
#pragma unroll
    for (int j = 0; j < 32; j++) acc[j] = 0.f;

    const int qb = tid >> 4;
    const int kb = tid & 15;

    const int ntiles = q0 / BKT + 1;
    for (int kt = 0; kt < ntiles; kt++) {
        const int k0 = kt * BKT;
        for (int idx = tid; idx < BKT * DQK_; idx += 256) {
            int kj = idx / DQK_, d = idx % DQK_;
            int t = b * S_ + k0 + kj;
            float v;
            if (d < DN_) v = gkv[(size_t)t * (H_ * 256) + h * 256 + d];
            else         v = gkvall[(size_t)t * (KVL_ + DR_) + KVL_ + (d - DN_)];
            Ks[kj * QSS + d] = v;
        }
        for (int idx = tid; idx < BKT * DV_; idx += 256) {
            int kj = idx / DV_, d = idx % DV_;
            int t = b * S_ + k0 + kj;
            Vs[kj * VSS + d] = gkv[(size_t)t * (H_ * 256) + h * 256 + DN_ + d];
        }
        __syncthreads();

        float sc[4][4];
#pragma unroll
        for (int i = 0; i < 4; i++)
#pragma unroll
            for (int j = 0; j < 4; j++) sc[i][j] = 0.f;

        const float* qp = &Qs[(qb * 4) * QSS];
        const float* kp = &Ks[(kb * 4) * QSS];
        for (int d = 0; d < DQK_; d += 4) {
            float4 ra[4], rb[4];
#pragma unroll
            for (int i = 0; i < 4; i++)
                ra[i] = *reinterpret_cast<const float4*>(&qp[i * QSS + d]);
#pragma unroll
            for (int j = 0; j < 4; j++)
                rb[j] = *reinterpret_cast<const float4*>(&kp[j * QSS + d]);
#pragma unroll
            for (int i = 0; i < 4; i++)
#pragma unroll
                for (int j = 0; j < 4; j++) {
                    sc[i][j] = fmaf(ra[i].x, rb[j].x, sc[i][j]);
                    sc[i][j] = fmaf(ra[i].y, rb[j].y, sc[i][j]);
                    sc[i][j] = fmaf(ra[i].z, rb[j].z, sc[i][j]);
                    sc[i][j] = fmaf(ra[i].w, rb[j].w, sc[i][j]);
                }
        }
#pragma unroll
        for (int i = 0; i < 4; i++)
#pragma unroll
            for (int j = 0; j < 4; j++) {
                int qg = q0 + qb * 4 + i;
                int kg = k0 + kb * 4 + j;
                Ss[(qb * 4 + i) * SSS + kb * 4 + j] = (kg <= qg) ? sc[i][j] : -1e30f;
            }
        __syncthreads();

        if (hd == 0) {
            float mnew = m;
            for (int kj = 0; kj < BKT; kj++)
                mnew = fmaxf(mnew, Ss[qi_own * SSS + kj]);
            float c = __expf(m - mnew);
            float ls = 0.f;
            for (int kj = 0; kj < BKT; kj++) {
                float p = __expf(Ss[qi_own * SSS + kj] - mnew);
                Ss[qi_own * SSS + kj] = p;
                ls += p;
            }
            l = l * c + ls;
            m = mnew;
            corr_s[qi_own] = c;
        }
        __syncthreads();

        {
            float c = corr_s[qi_own];
#pragma unroll
            for (int j = 0; j < 32; j++) acc[j] *= c;
            for (int kj = 0; kj < BKT; kj++) {
                float p = Ss[qi_own * SSS + kj];
                const float4* vp = reinterpret_cast<const float4*>(&Vs[kj * VSS + d0]);
#pragma unroll
                for (int j4 = 0; j4 < 8; j4++) {
                    float4 v = vp[j4];
                    acc[j4 * 4 + 0] = fmaf(p, v.x, acc[j4 * 4 + 0]);
                    acc[j4 * 4 + 1] = fmaf(p, v.y, acc[j4 * 4 + 1]);
                    acc[j4 * 4 + 2] = fmaf(p, v.z, acc[j4 * 4 + 2]);
                    acc[j4 * 4 + 3] = fmaf(p, v.w, acc[j4 * 4 + 3]);
                }
            }
        }
        __syncthreads();
    }

    if (hd == 0) linv_s[qi_own] = 1.f / l;
    __syncthreads();
    const float li = linv_s[qi_own];
    const int t = b * S_ + q0 + qi_own;
    float* outp = &gout[(size_t)t * (H_ * DV_) + h * DV_ + d0];
#pragma unroll
    for (int j = 0; j < 32; j++) outp[j] = acc[j] * li;
}

// ---------------- launcher ----------------
static inline void conv(const float* s, bf16* h, bf16* l, size_t n) {
    size_t n4 = n / 4;
    convert_split<<<(unsigned)((n4 + 255) / 256), 256>>>(s, h, l, n4);
}

static inline void gemm(const bf16* ah, const bf16* al, const bf16* wh, const bf16* wl,
                        float* c, int N, int K, int ldc) {
    dim3 grid((N + 127) / 128, NT_ / 128);
    gemm_hmma<<<grid, 256, GSMEM>>>(ah, al, wh, wl, c, N, K, ldc);
}

extern "C" void kernel_launch(void* const* d_in, const int* in_sizes, int n_in,
                              void* d_out, int out_size)
{
    const float* x      = (const float*)d_in[0];
    const float* freqs  = (const float*)d_in[1];
    const float* wq_a   = (const float*)d_in[2];
    const float* q_an_w = (const float*)d_in[3];
    const float* wq_b   = (const float*)d_in[4];
    const float* wkv_a  = (const float*)d_in[5];
    const float* kv_n_w = (const float*)d_in[6];
    const float* wkv_b  = (const float*)d_in[7];
    const float* wo     = (const float*)d_in[8];
    float* out = (float*)d_out;

    float *qan, *q, *kvall, *kv, *attn;
    cudaGetSymbolAddress((void**)&qan,   g_qan);
    cudaGetSymbolAddress((void**)&q,     g_q);
    cudaGetSymbolAddress((void**)&kvall, g_kvall);
    cudaGetSymbolAddress((void**)&kv,    g_kv);
    cudaGetSymbolAddress((void**)&attn,  g_attn);

    bf16 *xhi,*xlo,*qanhi,*qanlo,*kvnhi,*kvnlo,*athi,*atlo;
    bf16 *wqahi,*wqalo,*wqbhi,*wqblo,*wkvahi,*wkvalo,*wkvbhi,*wkvblo,*wohi,*wolo;
    cudaGetSymbolAddress((void**)&xhi, g_xhi);     cudaGetSymbolAddress((void**)&xlo, g_xlo);
    cudaGetSymbolAddress((void**)&qanhi, g_qanhi); cudaGetSymbolAddress((void**)&qanlo, g_qanlo);
    cudaGetSymbolAddress((void**)&kvnhi, g_kvnhi); cudaGetSymbolAddress((void**)&kvnlo, g_kvnlo);
    cudaGetSymbolAddress((void**)&athi, g_athi);   cudaGetSymbolAddress((void**)&atlo, g_atlo);
    cudaGetSymbolAddress((void**)&wqahi, g_wqahi); cudaGetSymbolAddress((void**)&wqalo, g_wqalo);
    cudaGetSymbolAddress((void**)&wqbhi, g_wqbhi); cudaGetSymbolAddress((void**)&wqblo, g_wqblo);
    cudaGetSymbolAddress((void**)&wkvahi, g_wkvahi); cudaGetSymbolAddress((void**)&wkvalo, g_wkvalo);
    cudaGetSymbolAddress((void**)&wkvbhi, g_wkvbhi); cudaGetSymbolAddress((void**)&wkvblo, g_wkvblo);
    cudaGetSymbolAddress((void**)&wohi, g_wohi);   cudaGetSymbolAddress((void**)&wolo, g_wolo);

    cudaFuncSetAttribute(attn_kernel, cudaFuncAttributeMaxDynamicSharedMemorySize, SMEM_BYTES);
    cudaFuncSetAttribute(gemm_hmma, cudaFuncAttributeMaxDynamicSharedMemorySize, GSMEM);

    // pre-convert inputs & weights to hi/lo bf16 planes
    conv(x,     xhi,   xlo,   (size_t)NT_ * HID_);
    conv(wq_a,  wqahi, wqalo, (size_t)QL_ * HID_);
    conv(wq_b,  wqbhi, wqblo, (size_t)(H_*DQK_) * QL_);
    conv(wkv_a, wkvahi,wkvalo,(size_t)(KVL_+DR_) * HID_);
    conv(wkv_b, wkvbhi,wkvblo,(size_t)(H_*256) * KVL_);
    conv(wo,    wohi,  wolo,  (size_t)HID_ * (H_*DV_));

    // 1. q_a = x @ wq_a^T
    gemm(xhi, xlo, wqahi, wqalo, qan, QL_, HID_, QL_);
    // 2. rmsnorm + convert
    rmsnorm_kernel<<<NT_, 256>>>(qan, q_an_w, QL_, QL_);
    conv(qan, qanhi, qanlo, (size_t)NT_ * QL_);
    // 3. q = q_a_n @ wq_b^T
    gemm(qanhi, qanlo, wqbhi, wqblo, q, H_ * DQK_, QL_, H_ * DQK_);
    // 4. rope q
    rope_q_kernel<<<dim3(NT_, H_), 32>>>(q, freqs);
    // 5. kv_all = x @ wkv_a^T
    gemm(xhi, xlo, wkvahi, wkvalo, kvall, KVL_ + DR_, HID_, KVL_ + DR_);
    // 6. rope k, rmsnorm kv_lat
    rope_k_kernel<<<NT_, 32>>>(kvall, freqs);
    rmsnorm_kernel<<<NT_, 256>>>(kvall, kv_n_w, KVL_, KVL_ + DR_);
    // 7. convert normed latents + kv = kvn @ wkv_b^T
    convert_split_kvn<<<(NT_ * 128 + 255) / 256, 256>>>(kvall, kvnhi, kvnlo);
    gemm(kvnhi, kvnlo, wkvbhi, wkvblo, kv, H_ * 256, KVL_, H_ * 256);
    // 8. attention (fp32)
    attn_kernel<<<dim3(S_ / BQ, H_, B_), 256, SMEM_BYTES>>>(q, kv, kvall, attn);
    // 9. convert + out = attn @ wo^T
    conv(attn, athi, atlo, (size_t)NT_ * (H_ * DV_));
    gemm(athi, atlo, wohi, wolo, out, HID_, H_ * DV_, HID_);
}

// round 4
// speedup vs baseline: 3.7450x; 2.7702x over previous
#include <cuda_runtime.h>
#include <cuda_bf16.h>
#include <cstdint>

// ---------------- problem constants ----------------
#define B_   2
#define S_   2048
#define HID_ 2048
#define H_   16
#define QL_  1536
#define KVL_ 512
#define DN_  128
#define DR_  64
#define DV_  128
#define DQK_ 192
#define NT_  (B_*S_)        // 4096 tokens

typedef __nv_bfloat16 bf16;

// ---------------- scratch (static device globals; no alloc) ----------------
__device__ __align__(128) float g_qan[(size_t)NT_ * QL_];
__device__ __align__(128) float g_q[(size_t)NT_ * (H_ * DQK_)];
__device__ __align__(128) float g_kvall[(size_t)NT_ * (KVL_ + DR_)];
__device__ __align__(128) float g_kv[(size_t)NT_ * (H_ * (DN_ + DV_))];
__device__ __align__(128) float g_attn[(size_t)NT_ * (H_ * DV_)];

__device__ __align__(128) bf16 g_xhi[(size_t)NT_ * HID_],  g_xlo[(size_t)NT_ * HID_];
__device__ __align__(128) bf16 g_qanhi[(size_t)NT_ * QL_], g_qanlo[(size_t)NT_ * QL_];
__device__ __align__(128) bf16 g_kvnhi[(size_t)NT_ * KVL_],g_kvnlo[(size_t)NT_ * KVL_];
__device__ __align__(128) bf16 g_athi[(size_t)NT_ * (H_*DV_)], g_atlo[(size_t)NT_ * (H_*DV_)];
__device__ __align__(128) bf16 g_wqahi[(size_t)QL_ * HID_],        g_wqalo[(size_t)QL_ * HID_];
__device__ __align__(128) bf16 g_wqbhi[(size_t)(H_*DQK_) * QL_],   g_wqblo[(size_t)(H_*DQK_) * QL_];
__device__ __align__(128) bf16 g_wkvahi[(size_t)(KVL_+DR_) * HID_],g_wkvalo[(size_t)(KVL_+DR_) * HID_];
__device__ __align__(128) bf16 g_wkvbhi[(size_t)(H_*256) * KVL_],  g_wkvblo[(size_t)(H_*256) * KVL_];
__device__ __align__(128) bf16 g_wohi[(size_t)HID_ * (H_*DV_)],    g_wolo[(size_t)HID_ * (H_*DV_)];

// attention operand planes, packed per head
__device__ __align__(128) bf16 g_aqhi[(size_t)NT_ * H_ * DQK_], g_aqlo[(size_t)NT_ * H_ * DQK_];
__device__ __align__(128) bf16 g_akhi[(size_t)NT_ * H_ * DQK_], g_aklo[(size_t)NT_ * H_ * DQK_];
__device__ __align__(128) bf16 g_avhi[(size_t)NT_ * H_ * DV_],  g_avlo[(size_t)NT_ * H_ * DV_];

// ================= PTX helpers (baseline compute_103 features only) =========
__device__ __forceinline__ uint32_t smem_u32(const void* p) {
    uint32_t a;
    asm("{ .reg .u64 t; cvta.to.shared.u64 t, %1; cvt.u32.u64 %0, t; }" : "=r"(a) : "l"(p));
    return a;
}
__device__ __forceinline__ void cp_async16(uint32_t dst, const void* src, int src_bytes) {
    asm volatile("cp.async.cg.shared.global [%0], [%1], 16, %2;"
                 :: "r"(dst), "l"(src), "r"(src_bytes) : "memory");
}
__device__ __forceinline__ void cp_commit() {
    asm volatile("cp.async.commit_group;" ::: "memory");
}
template <int N>
__device__ __forceinline__ void cp_wait() {
    asm volatile("cp.async.wait_group %0;" :: "n"(N) : "memory");
}
__device__ __forceinline__ void ldmx4(uint32_t* r, uint32_t addr) {
    asm volatile("ldmatrix.sync.aligned.m8n8.x4.shared.b16 {%0,%1,%2,%3}, [%4];"
                 : "=r"(r[0]), "=r"(r[1]), "=r"(r[2]), "=r"(r[3]) : "r"(addr));
}
__device__ __forceinline__ void ldmx4t(uint32_t* r, uint32_t addr) {
    asm volatile("ldmatrix.sync.aligned.m8n8.x4.trans.shared.b16 {%0,%1,%2,%3}, [%4];"
                 : "=r"(r[0]), "=r"(r[1]), "=r"(r[2]), "=r"(r[3]) : "r"(addr));
}
// non-volatile: pure register op, lets ptxas interleave independent chains
__device__ __forceinline__ void mma16816(float* c, const uint32_t* a, uint32_t b0, uint32_t b1) {
    asm("mma.sync.aligned.m16n8k16.row.col.f32.bf16.bf16.f32 "
        "{%0,%1,%2,%3}, {%4,%5,%6,%7}, {%8,%9}, {%0,%1,%2,%3};"
        : "+f"(c[0]), "+f"(c[1]), "+f"(c[2]), "+f"(c[3])
        : "r"(a[0]), "r"(a[1]), "r"(a[2]), "r"(a[3]), "r"(b0), "r"(b1));
}
// pack two fp32 -> bf16x2 (x -> low half, y -> high half)
__device__ __forceinline__ uint32_t packbf(float x, float y) {
    uint32_t r;
    asm("cvt.rn.bf16x2.f32 %0, %1, %2;" : "=r"(r) : "f"(y), "f"(x));
    return r;
}
__device__ __forceinline__ void split2(float x, float y, uint32_t& hi, uint32_t& lo) {
    float xh = __bfloat162float(__float2bfloat16(x));
    float yh = __bfloat162float(__float2bfloat16(y));
    hi = packbf(xh, yh);
    lo = packbf(x - xh, y - yh);
}

// ================= HMMA split-bf16 GEMM ======================================
#define GBK 32
#define ROWB 80
#define PLANE (128 * ROWB)
#define GBUF  (4 * PLANE)
#define GSMEM (2 * GBUF)

__device__ __forceinline__ void load_tile(
    const bf16* __restrict__ g, int ld, int rowbase, int rowlim,
    int kcol, uint32_t sdst, int tid)
{
#pragma unroll
    for (int i = 0; i < 2; ++i) {
        int idx = tid + i * 256;
        int r = idx >> 2;
        int c8 = (idx & 3) << 3;
        int gr = rowbase + r;
        int ok = (gr < rowlim);
        const bf16* src = g + (size_t)(ok ? gr : rowbase) * ld + kcol + c8;
        cp_async16(sdst + r * ROWB + c8 * 2, src, ok ? 16 : 0);
    }
}

extern __shared__ uint8_t dsm[];

__global__ __launch_bounds__(256, 2) void gemm_hmma(
    const bf16* __restrict__ Ahi, const bf16* __restrict__ Alo,
    const bf16* __restrict__ Whi, const bf16* __restrict__ Wlo,
    float* __restrict__ C, int N, int K, int ldc)
{
    const int tid  = threadIdx.x;
    const int wid  = tid >> 5;
    const int lane = tid & 31;
    const int bm = blockIdx.y * 128;
    const int bn = blockIdx.x * 128;
    const int wm = (wid & 3) * 32;
    const int wn = (wid >> 2) * 64;
    const uint32_t sb = smem_u32(dsm);

    float acc[2][8][4];
#pragma unroll
    for (int i = 0; i < 2; i++)
#pragma unroll
        for (int j = 0; j < 8; j++)
#pragma unroll
            for (int k = 0; k < 4; k++) acc[i][j][k] = 0.f;

    const int nchunks = K / GBK;

    {
        uint32_t buf = sb;
        load_tile(Ahi, K, bm, 1 << 30, 0, buf,             tid);
        load_tile(Alo, K, bm, 1 << 30, 0, buf + PLANE,     tid);
        load_tile(Whi, K, bn, N,       0, buf + 2 * PLANE, tid);
        load_tile(Wlo, K, bn, N,       0, buf + 3 * PLANE, tid);
        cp_commit();
    }

    const uint32_t a_off = (uint32_t)((wm + (lane & 15)) * ROWB + ((lane >> 4) << 3) * 2);
    const uint32_t b_off = (uint32_t)((wn + (lane & 7)) * ROWB + ((lane >> 3) << 3) * 2);

    for (int c = 0; c < nchunks; ++c) {
        if (c + 1 < nchunks) {
            uint32_t buf = sb + ((c + 1) & 1) * GBUF;
            int kcol = (c + 1) * GBK;
            load_tile(Ahi, K, bm, 1 << 30, kcol, buf,             tid);
            load_tile(Alo, K, bm, 1 << 30, kcol, buf + PLANE,     tid);
            load_tile(Whi, K, bn, N,       kcol, buf + 2 * PLANE, tid);
            load_tile(Wlo, K, bn, N,       kcol, buf + 3 * PLANE, tid);
            cp_commit();
            cp_wait<1>();
        } else {
            cp_wait<0>();
        }
        __syncthreads();

        const uint32_t buf = sb + (c & 1) * GBUF;

        uint32_t afr[2][2][2][4];
#pragma unroll
        for (int pl = 0; pl < 2; ++pl)
#pragma unroll
            for (int mi = 0; mi < 2; ++mi)
#pragma unroll
                for (int kf = 0; kf < 2; ++kf)
                    ldmx4(afr[pl][mi][kf],
                          buf + pl * PLANE + a_off + mi * 16 * ROWB + kf * 32);

#pragma unroll
        for (int ni = 0; ni < 8; ++ni) {
            uint32_t bhi[4], blo[4];
            ldmx4(bhi, buf + 2 * PLANE + b_off + ni * 8 * ROWB);
            ldmx4(blo, buf + 3 * PLANE + b_off + ni * 8 * ROWB);
#pragma unroll
            for (int mi = 0; mi < 2; ++mi) {
                float* d = acc[mi][ni];
                mma16816(d, afr[0][mi][0], bhi[0], bhi[1]);
                mma16816(d, afr[0][mi][1], bhi[2], bhi[3]);
                mma16816(d, afr[0][mi][0], blo[0], blo[1]);
                mma16816(d, afr[0][mi][1], blo[2], blo[3]);
                mma16816(d, afr[1][mi][0], bhi[0], bhi[1]);
                mma16816(d, afr[1][mi][1], bhi[2], bhi[3]);
            }
        }
        __syncthreads();
    }

    const int r0 = bm + wm + (lane >> 2);
    const int cb = bn + wn + (lane & 3) * 2;
#pragma unroll
    for (int mi = 0; mi < 2; ++mi)
#pragma unroll
        for (int ni = 0; ni < 8; ++ni) {
            int col = cb + ni * 8;
            if (col < N) {
                int row = r0 + mi * 16;
                *reinterpret_cast<float2*>(&C[(size_t)row * ldc + col]) =
                    make_float2(acc[mi][ni][0], acc[mi][ni][1]);
                *reinterpret_cast<float2*>(&C[(size_t)(row + 8) * ldc + col]) =
                    make_float2(acc[mi][ni][2], acc[mi][ni][3]);
            }
        }
}

// ================= converts =================
__global__ void convert_split(const float* __restrict__ src,
                              bf16* __restrict__ hi, bf16* __restrict__ lo, size_t n4)
{
    size_t i = (size_t)blockIdx.x * blockDim.x + threadIdx.x;
    if (i >= n4) return;
    float4 v = reinterpret_cast<const float4*>(src)[i];
    bf16 h0 = __float2bfloat16(v.x), h1 = __float2bfloat16(v.y);
    bf16 h2 = __float2bfloat16(v.z), h3 = __float2bfloat16(v.w);
    bf16 l0 = __float2bfloat16(v.x - __bfloat162float(h0));
    bf16 l1 = __float2bfloat16(v.y - __bfloat162float(h1));
    bf16 l2 = __float2bfloat16(v.z - __bfloat162float(h2));
    bf16 l3 = __float2bfloat16(v.w - __bfloat162float(h3));
    __nv_bfloat162* hp = reinterpret_cast<__nv_bfloat162*>(hi);
    __nv_bfloat162* lp = reinterpret_cast<__nv_bfloat162*>(lo);
    hp[2*i]   = __nv_bfloat162(h0, h1); hp[2*i+1] = __nv_bfloat162(h2, h3);
    lp[2*i]   = __nv_bfloat162(l0, l1); lp[2*i+1] = __nv_bfloat162(l2, l3);
}

__global__ void convert_split_kvn(const float* __restrict__ src,
                                  bf16* __restrict__ hi, bf16* __restrict__ lo)
{
    size_t i = (size_t)blockIdx.x * blockDim.x + threadIdx.x;
    if (i >= (size_t)NT_ * 128) return;
    size_t r = i >> 7, c4 = i & 127;
    float4 v = *reinterpret_cast<const float4*>(&src[r * (KVL_ + DR_) + c4 * 4]);
    bf16 h0 = __float2bfloat16(v.x), h1 = __float2bfloat16(v.y);
    bf16 h2 = __float2bfloat16(v.z), h3 = __float2bfloat16(v.w);
    bf16 l0 = __float2bfloat16(v.x - __bfloat162float(h0));
    bf16 l1 = __float2bfloat16(v.y - __bfloat162float(h1));
    bf16 l2 = __float2bfloat16(v.z - __bfloat162float(h2));
    bf16 l3 = __float2bfloat16(v.w - __bfloat162float(h3));
    size_t o = r * KVL_ + c4 * 4;
    __nv_bfloat162* hp = reinterpret_cast<__nv_bfloat162*>(&hi[o]);
    __nv_bfloat162* lp = reinterpret_cast<__nv_bfloat162*>(&lo[o]);
    hp[0] = __nv_bfloat162(h0, h1); hp[1] = __nv_bfloat162(h2, h3);
    lp[0] = __nv_bfloat162(l0, l1); lp[1] = __nv_bfloat162(l2, l3);
}

// q (post-rope) -> scaled bf16 hi/lo planes; layout identical linear index
__global__ void convert_q_attn(const float* __restrict__ src,
                               bf16* __restrict__ hi, bf16* __restrict__ lo)
{
    size_t i = (size_t)blockIdx.x * blockDim.x + threadIdx.x;
    if (i >= (size_t)NT_ * H_ * DQK_ / 4) return;
    float4 v = reinterpret_cast<const float4*>(src)[i];
    const float sc = 0.07216878364870323f;   // 1/sqrt(192)
    v.x *= sc; v.y *= sc; v.z *= sc; v.w *= sc;
    bf16 h0 = __float2bfloat16(v.x), h1 = __float2bfloat16(v.y);
    bf16 h2 = __float2bfloat16(v.z), h3 = __float2bfloat16(v.w);
    bf16 l0 = __float2bfloat16(v.x - __bfloat162float(h0));
    bf16 l1 = __float2bfloat16(v.y - __bfloat162float(h1));
    bf16 l2 = __float2bfloat16(v.z - __bfloat162float(h2));
    bf16 l3 = __float2bfloat16(v.w - __bfloat162float(h3));
    __nv_bfloat162* hp = reinterpret_cast<__nv_bfloat162*>(hi);
    __nv_bfloat162* lp = reinterpret_cast<__nv_bfloat162*>(lo);
    hp[2*i]   = __nv_bfloat162(h0, h1); hp[2*i+1] = __nv_bfloat162(h2, h3);
    lp[2*i]   = __nv_bfloat162(l0, l1); lp[2*i+1] = __nv_bfloat162(l2, l3);
}

// build packed K planes [t][h][192]: d<128 from g_kv, d>=128 k_pe broadcast
__global__ void build_k_split(const float* __restrict__ gkv, const float* __restrict__ gkvall,
                              bf16* __restrict__ khi, bf16* __restrict__ klo)
{
    size_t i = (size_t)blockIdx.x * blockDim.x + threadIdx.x;  // over NT*H*48 groups
    if (i >= (size_t)NT_ * H_ * 48) return;
    int g = (int)(i % 48);
    size_t th = i / 48;
    int h = (int)(th % H_);
    size_t t = th / H_;
    int d = g * 4;
    float4 v;
    if (d < 128) v = *reinterpret_cast<const float4*>(&gkv[t * (H_*256) + h * 256 + d]);
    else         v = *reinterpret_cast<const float4*>(&gkvall[t * (KVL_+DR_) + KVL_ + d - 128]);
    bf16 h0 = __float2bfloat16(v.x), h1 = __float2bfloat16(v.y);
    bf16 h2 = __float2bfloat16(v.z), h3 = __float2bfloat16(v.w);
    bf16 l0 = __float2bfloat16(v.x - __bfloat162float(h0));
    bf16 l1 = __float2bfloat16(v.y - __bfloat162float(h1));
    bf16 l2 = __float2bfloat16(v.z - __bfloat162float(h2));
    bf16 l3 = __float2bfloat16(v.w - __bfloat162float(h3));
    size_t o = (t * H_ + h) * 192 + d;
    __nv_bfloat162* hp = reinterpret_cast<__nv_bfloat162*>(&khi[o]);
    __nv_bfloat162* lp = reinterpret_cast<__nv_bfloat162*>(&klo[o]);
    hp[0] = __nv_bfloat162(h0, h1); hp[1] = __nv_bfloat162(h2, h3);
    lp[0] = __nv_bfloat162(l0, l1); lp[1] = __nv_bfloat162(l2, l3);
}

__global__ void build_v_split(const float* __restrict__ gkv,
                              bf16* __restrict__ vhi, bf16* __restrict__ vlo)
{
    size_t i = (size_t)blockIdx.x * blockDim.x + threadIdx.x;  // over NT*H*32 groups
    if (i >= (size_t)NT_ * H_ * 32) return;
    int g = (int)(i % 32);
    size_t th = i / 32;
    int h = (int)(th % H_);
    size_t t = th / H_;
    int d = g * 4;
    float4 v = *reinterpret_cast<const float4*>(&gkv[t * (H_*256) + h * 256 + 128 + d]);
    bf16 h0 = __float2bfloat16(v.x), h1 = __float2bfloat16(v.y);
    bf16 h2 = __float2bfloat16(v.z), h3 = __float2bfloat16(v.w);
    bf16 l0 = __float2bfloat16(v.x - __bfloat162float(h0));
    bf16 l1 = __float2bfloat16(v.y - __bfloat162float(h1));
    bf16 l2 = __float2bfloat16(v.z - __bfloat162float(h2));
    bf16 l3 = __float2bfloat16(v.w - __bfloat162float(h3));
    size_t o = (t * H_ + h) * 128 + d;
    __nv_bfloat162* hp = reinterpret_cast<__nv_bfloat162*>(&vhi[o]);
    __nv_bfloat162* lp = reinterpret_cast<__nv_bfloat162*>(&vlo[o]);
    hp[0] = __nv_bfloat162(h0, h1); hp[1] = __nv_bfloat162(h2, h3);
    lp[0] = __nv_bfloat162(l0, l1); lp[1] = __nv_bfloat162(l2, l3);
}

// ---------------- RMSNorm ----------------
__global__ void rmsnorm_kernel(float* __restrict__ x, const float* __restrict__ w,
                               int n, int stride)
{
    const int row = blockIdx.x;
    float* p = x + (size_t)row * stride;
    __shared__ float red[256];
    float s = 0.f;
    for (int i = threadIdx.x; i < n; i += 256) { float v = p[i]; s += v * v; }
    red[threadIdx.x] = s;
    __syncthreads();
    for (int o = 128; o > 0; o >>= 1) {
        if (threadIdx.x < o) red[threadIdx.x] += red[threadIdx.x + o];
        __syncthreads();
    }
    float inv = rsqrtf(red[0] / n + 1e-6f);
    for (int i = threadIdx.x; i < n; i += 256) p[i] = p[i] * inv * w[i];
}

// ---------------- RoPE ----------------
__global__ void rope_q_kernel(float* __restrict__ q, const float* __restrict__ fc)
{
    const int t = blockIdx.x, h = blockIdx.y, i = threadIdx.x;
    const int s = t & (S_ - 1);
    const float c  = fc[(s * 32 + i) * 2 + 0];
    const float sn = fc[(s * 32 + i) * 2 + 1];
    float* base = q + (size_t)t * (H_ * DQK_) + h * DQK_ + DN_;
    float xr = base[2 * i], xi = base[2 * i + 1];
    base[2 * i]     = xr * c - xi * sn;
    base[2 * i + 1] = xr * sn + xi * c;
}
__global__ void rope_k_kernel(float* __restrict__ kva, const float* __restrict__ fc)
{
    const int t = blockIdx.x, i = threadIdx.x;
    const int s = t & (S_ - 1);
    const float c  = fc[(s * 32 + i) * 2 + 0];
    const float sn = fc[(s * 32 + i) * 2 + 1];
    float* base = kva + (size_t)t * (KVL_ + DR_) + KVL_;
    float xr = base[2 * i], xi = base[2 * i + 1];
    base[2 * i]     = xr * c - xi * sn;
    base[2 * i + 1] = xr * sn + xi * c;
}

// ================= HMMA flash attention =====================================
// BQ=64, BK=64, 128 threads (4 warps), warp = 16 q-rows x full 64 keys.
// smem (bf16 elems): Qhi[64x200] Qlo | 2 stages of {Khi,Klo[64x200], Vhi,Vlo[64x136]}
#define AQP 200
#define AVP 136
#define SM_QLO 12800
#define SM_ST  25600
#define STG_EL 43008
#define ATT_SMEM ((SM_ST + 2 * STG_EL) * 2)   // 223232 bytes

__global__ __launch_bounds__(128, 1) void attn_hmma(
    const bf16* __restrict__ qhi, const bf16* __restrict__ qlo,
    const bf16* __restrict__ khi, const bf16* __restrict__ klo,
    const bf16* __restrict__ vhi, const bf16* __restrict__ vlo,
    float* __restrict__ gout)
{
    extern __shared__ bf16 asmem[];
    const int qt = gridDim.x - 1 - blockIdx.x;    // long CTAs first
    const int h = blockIdx.y, b = blockIdx.z;
    const int tid = threadIdx.x, wid = tid >> 5, lane = tid & 31;
    const int q0 = qt * 64;
    const uint32_t sb = smem_u32(asmem);

    // Q tile hi/lo via cp.async (group 0)
    for (int i = tid; i < 1536; i += 128) {
        int r = i / 24, c = (i % 24) * 8;
        size_t g = ((size_t)(b * S_ + q0 + r) * H_ + h) * 192 + c;
        uint32_t d = sb + (r * AQP + c) * 2;
        cp_async16(d, qhi + g, 16);
        cp_async16(d + SM_QLO * 2, qlo + g, 16);
    }
    cp_commit();

    auto load_kv = [&](int kt, int s) {
        const int k0 = kt * 64;
        const uint32_t st = sb + (SM_ST + s * STG_EL) * 2;
        for (int i = tid; i < 1536; i += 128) {
            int r = i / 24, c = (i % 24) * 8;
            size_t g = ((size_t)(b * S_ + k0 + r) * H_ + h) * 192 + c;
            uint32_t d = st + (r * AQP + c) * 2;
            cp_async16(d, khi + g, 16);
            cp_async16(d + 12800 * 2, klo + g, 16);
        }
        for (int i = tid; i < 1024; i += 128) {
            int r = i / 16, c = (i % 16) * 8;
            size_t g = ((size_t)(b * S_ + k0 + r) * H_ + h) * 128 + c;
            uint32_t d = st + 25600 * 2 + (r * AVP + c) * 2;
            cp_async16(d, vhi + g, 16);
            cp_async16(d + 8704 * 2, vlo + g, 16);
        }
        cp_commit();
    };

    float oa[16][4];
#pragma unroll
    for (int j = 0; j < 16; j++)
#pragma unroll
        for (int e = 0; e < 4; e++) oa[j][e] = 0.f;
    float m0 = -1e30f, m1 = -1e30f, l0 = 0.f, l1 = 0.f;

    const int ntiles = qt + 1;
    load_kv(0, 0);

    const uint32_t qoff = sb + ((wid * 16 + (lane & 15)) * AQP + (lane >> 4) * 8) * 2;

    for (int kt = 0; kt < ntiles; kt++) {
        if (kt + 1 < ntiles) { load_kv(kt + 1, (kt + 1) & 1); cp_wait<1>(); }
        else                 { cp_wait<0>(); }
        __syncthreads();
        const uint32_t st = sb + (SM_ST + (kt & 1) * STG_EL) * 2;

        // ---- scores: S = Qhi*Khi + Qhi*Klo + Qlo*Khi ----
        float c[8][4];
#pragma unroll
        for (int j = 0; j < 8; j++)
#pragma unroll
            for (int e = 0; e < 4; e++) c[j][e] = 0.f;

        const uint32_t kb = st + ((lane & 7) * AQP + (lane >> 3) * 8) * 2;
#pragma unroll
        for (int kp = 0; kp < 6; kp++) {
            uint32_t qh[2][4], ql[2][4];
            ldmx4(qh[0], qoff + kp * 64);
            ldmx4(qh[1], qoff + kp * 64 + 32);
            ldmx4(ql[0], qoff + SM_QLO * 2 + kp * 64);
            ldmx4(ql[1], qoff + SM_QLO * 2 + kp * 64 + 32);
#pragma unroll
            for (int nb = 0; nb < 8; nb++) {
                uint32_t kh[4], kl[4];
                ldmx4(kh, kb + nb * 8 * AQP * 2 + kp * 64);
                ldmx4(kl, kb + 12800 * 2 + nb * 8 * AQP * 2 + kp * 64);
                mma16816(c[nb], qh[0], kh[0], kh[1]);
                mma16816(c[nb], qh[1], kh[2], kh[3]);
                mma16816(c[nb], qh[0], kl[0], kl[1]);
                mma16816(c[nb], qh[1], kl[2], kl[3]);
                mma16816(c[nb], ql[0], kh[0], kh[1]);
                mma16816(c[nb], ql[1], kh[2], kh[3]);
            }
        }

        // ---- causal mask (diagonal tile only) ----
        if (kt == qt) {
            const int r0 = wid * 16 + (lane >> 2);
            const int cbase = (lane & 3) * 2;
#pragma unroll
            for (int nb = 0; nb < 8; nb++) {
                int col = nb * 8 + cbase;
                if (col     > r0    ) c[nb][0] = -1e30f;
                if (col + 1 > r0    ) c[nb][1] = -1e30f;
                if (col     > r0 + 8) c[nb][2] = -1e30f;
                if (col + 1 > r0 + 8) c[nb][3] = -1e30f;
            }
        }

        // ---- online softmax (rows lane>>2 and +8; 4-lane groups) ----
        float mx0 = -1e30f, mx1 = -1e30f;
#pragma unroll
        for (int nb = 0; nb < 8; nb++) {
            mx0 = fmaxf(mx0, fmaxf(c[nb][0], c[nb][1]));
            mx1 = fmaxf(mx1, fmaxf(c[nb][2], c[nb][3]));
        }
        mx0 = fmaxf(mx0, __shfl_xor_sync(0xffffffffu, mx0, 1));
        mx0 = fmaxf(mx0, __shfl_xor_sync(0xffffffffu, mx0, 2));
        mx1 = fmaxf(mx1, __shfl_xor_sync(0xffffffffu, mx1, 1));
        mx1 = fmaxf(mx1, __shfl_xor_sync(0xffffffffu, mx1, 2));
        float mn0 = fmaxf(m0, mx0), mn1 = fmaxf(m1, mx1);
        float co0 = __expf(m0 - mn0), co1 = __expf(m1 - mn1);
        m0 = mn0; m1 = mn1;
        float s0 = 0.f, s1 = 0.f;
#pragma unroll
        for (int nb = 0; nb < 8; nb++) {
            c[nb][0] = __expf(c[nb][0] - mn0); s0 += c[nb][0];
            c[nb][1] = __expf(c[nb][1] - mn0); s0 += c[nb][1];
            c[nb][2] = __expf(c[nb][2] - mn1); s1 += c[nb][2];
            c[nb][3] = __expf(c[nb][3] - mn1); s1 += c[nb][3];
        }
        s0 += __shfl_xor_sync(0xffffffffu, s0, 1);
        s0 += __shfl_xor_sync(0xffffffffu, s0, 2);
        s1 += __shfl_xor_sync(0xffffffffu, s1, 1);
        s1 += __shfl_xor_sync(0xffffffffu, s1, 2);
        l0 = l0 * co0 + s0;
        l1 = l1 * co1 + s1;
#pragma unroll
        for (int j = 0; j < 16; j++) {
            oa[j][0] *= co0; oa[j][1] *= co0;
            oa[j][2] *= co1; oa[j][3] *= co1;
        }

        // ---- O += Phi*Vhi + Plo*Vhi + Phi*Vlo ----
        const uint32_t vb = st + 25600 * 2 + ((lane & 15) * AVP + (lane >> 4) * 8) * 2;
#pragma unroll
        for (int kk = 0; kk < 4; kk++) {
            uint32_t ah[4], al[4];
            split2(c[2*kk][0],   c[2*kk][1],   ah[0], al[0]);
            split2(c[2*kk][2],   c[2*kk][3],   ah[1], al[1]);
            split2(c[2*kk+1][0], c[2*kk+1][1], ah[2], al[2]);
            split2(c[2*kk+1][2], c[2*kk+1][3], ah[3], al[3]);
#pragma unroll
            for (int n16 = 0; n16 < 8; n16++) {
                uint32_t vh[4], vl[4];
                ldmx4t(vh, vb + (kk * 16 * AVP + n16 * 16) * 2);
                ldmx4t(vl, vb + 8704 * 2 + (kk * 16 * AVP + n16 * 16) * 2);
                float* o0 = oa[2 * n16];
                float* o1 = oa[2 * n16 + 1];
                mma16816(o0, ah, vh[0], vh[1]);
                mma16816(o1, ah, vh[2], vh[3]);
                mma16816(o0, al, vh[0], vh[1]);
                mma16816(o1, al, vh[2], vh[3]);
                mma16816(o0, ah, vl[0], vl[1]);
                mma16816(o1, ah, vl[2], vl[3]);
            }
        }
        __syncthreads();
    }

    // ---- finalize & store ----
    const float i0 = 1.f / l0, i1 = 1.f / l1;
    const int r0 = q0 + wid * 16 + (lane >> 2);
    const size_t t0 = (size_t)(b * S_ + r0);
#pragma unroll
    for (int j = 0; j < 16; j++) {
        int col = h * 128 + j * 8 + (lane & 3) * 2;
        *reinterpret_cast<float2*>(&gout[t0 * (H_*DV_) + col]) =
            make_float2(oa[j][0] * i0, oa[j][1] * i0);
        *reinterpret_cast<float2*>(&gout[(t0 + 8) * (H_*DV_) + col]) =
            make_float2(oa[j][2] * i1, oa[j][3] * i1);
    }
}

// ---------------- launcher ----------------
static inline void conv(const float* s, bf16* h, bf16* l, size_t n) {
    size_t n4 = n / 4;
    convert_split<<<(unsigned)((n4 + 255) / 256), 256>>>(s, h, l, n4);
}

static inline void gemm(const bf16* ah, const bf16* al, const bf16* wh, const bf16* wl,
                        float* c, int N, int K, int ldc) {
    dim3 grid((N + 127) / 128, NT_ / 128);
    gemm_hmma<<<grid, 256, GSMEM>>>(ah, al, wh, wl, c, N, K, ldc);
}

extern "C" void kernel_launch(void* const* d_in, const int* in_sizes, int n_in,
                              void* d_out, int out_size)
{
    const float* x      = (const float*)d_in[0];
    const float* freqs  = (const float*)d_in[1];
    const float* wq_a   = (const float*)d_in[2];
    const float* q_an_w = (const float*)d_in[3];
    const float* wq_b   = (const float*)d_in[4];
    const float* wkv_a  = (const float*)d_in[5];
    const float* kv_n_w = (const float*)d_in[6];
    const float* wkv_b  = (const float*)d_in[7];
    const float* wo     = (const float*)d_in[8];
    float* out = (float*)d_out;

    float *qan, *q, *kvall, *kv, *attn;
    cudaGetSymbolAddress((void**)&qan,   g_qan);
    cudaGetSymbolAddress((void**)&q,     g_q);
    cudaGetSymbolAddress((void**)&kvall, g_kvall);
    cudaGetSymbolAddress((void**)&kv,    g_kv);
    cudaGetSymbolAddress((void**)&attn,  g_attn);

    bf16 *xhi,*xlo,*qanhi,*qanlo,*kvnhi,*kvnlo,*athi,*atlo;
    bf16 *wqahi,*wqalo,*wqbhi,*wqblo,*wkvahi,*wkvalo,*wkvbhi,*wkvblo,*wohi,*wolo;
    bf16 *aqhi,*aqlo,*akhi,*aklo,*avhi,*avlo;
    cudaGetSymbolAddress((void**)&xhi, g_xhi);     cudaGetSymbolAddress((void**)&xlo, g_xlo);
    cudaGetSymbolAddress((void**)&qanhi, g_qanhi); cudaGetSymbolAddress((void**)&qanlo, g_qanlo);
    cudaGetSymbolAddress((void**)&kvnhi, g_kvnhi); cudaGetSymbolAddress((void**)&kvnlo, g_kvnlo);
    cudaGetSymbolAddress((void**)&athi, g_athi);   cudaGetSymbolAddress((void**)&atlo, g_atlo);
    cudaGetSymbolAddress((void**)&wqahi, g_wqahi); cudaGetSymbolAddress((void**)&wqalo, g_wqalo);
    cudaGetSymbolAddress((void**)&wqbhi, g_wqbhi); cudaGetSymbolAddress((void**)&wqblo, g_wqblo);
    cudaGetSymbolAddress((void**)&wkvahi, g_wkvahi); cudaGetSymbolAddress((void**)&wkvalo, g_wkvalo);
    cudaGetSymbolAddress((void**)&wkvbhi, g_wkvbhi); cudaGetSymbolAddress((void**)&wkvblo, g_wkvblo);
    cudaGetSymbolAddress((void**)&wohi, g_wohi);   cudaGetSymbolAddress((void**)&wolo, g_wolo);
    cudaGetSymbolAddress((void**)&aqhi, g_aqhi);   cudaGetSymbolAddress((void**)&aqlo, g_aqlo);
    cudaGetSymbolAddress((void**)&akhi, g_akhi);   cudaGetSymbolAddress((void**)&aklo, g_aklo);
    cudaGetSymbolAddress((void**)&avhi, g_avhi);   cudaGetSymbolAddress((void**)&avlo, g_avlo);

    cudaFuncSetAttribute(gemm_hmma, cudaFuncAttributeMaxDynamicSharedMemorySize, GSMEM);
    cudaFuncSetAttribute(attn_hmma, cudaFuncAttributeMaxDynamicSharedMemorySize, ATT_SMEM);

    // pre-convert inputs & weights
    conv(x,     xhi,   xlo,   (size_t)NT_ * HID_);
    conv(wq_a,  wqahi, wqalo, (size_t)QL_ * HID_);
    conv(wq_b,  wqbhi, wqblo, (size_t)(H_*DQK_) * QL_);
    conv(wkv_a, wkvahi,wkvalo,(size_t)(KVL_+DR_) * HID_);
    conv(wkv_b, wkvbhi,wkvblo,(size_t)(H_*256) * KVL_);
    conv(wo,    wohi,  wolo,  (size_t)HID_ * (H_*DV_));

    // q path
    gemm(xhi, xlo, wqahi, wqalo, qan, QL_, HID_, QL_);
    rmsnorm_kernel<<<NT_, 256>>>(qan, q_an_w, QL_, QL_);
    conv(qan, qanhi, qanlo, (size_t)NT_ * QL_);
    gemm(qanhi, qanlo, wqbhi, wqblo, q, H_ * DQK_, QL_, H_ * DQK_);
    rope_q_kernel<<<dim3(NT_, H_), 32>>>(q, freqs);
    convert_q_attn<<<(NT_ * H_ * DQK_ / 4 + 255) / 256, 256>>>(q, aqhi, aqlo);

    // kv path
    gemm(xhi, xlo, wkvahi, wkvalo, kvall, KVL_ + DR_, HID_, KVL_ + DR_);
    rope_k_kernel<<<NT_, 32>>>(kvall, freqs);
    rmsnorm_kernel<<<NT_, 256>>>(kvall, kv_n_w, KVL_, KVL_ + DR_);
    convert_split_kvn<<<(NT_ * 128 + 255) / 256, 256>>>(kvall, kvnhi, kvnlo);
    gemm(kvnhi, kvnlo, wkvbhi, wkvblo, kv, H_ * 256, KVL_, H_ * 256);
    build_k_split<<<(NT_ * H_ * 48 + 255) / 256, 256>>>(kv, kvall, akhi, aklo);
    build_v_split<<<(NT_ * H_ * 32 + 255) / 256, 256>>>(kv, avhi, avlo);

    // attention
    attn_hmma<<<dim3(S_ / 64, H_, B_), 128, ATT_SMEM>>>(
        aqhi, aqlo, akhi, aklo, avhi, avlo, attn);

    // output projection
    conv(attn, athi, atlo, (size_t)NT_ * (H_ * DV_));
    gemm(athi, atlo, wohi, wolo, out, HID_, H_ * DV_, HID_);
}

// round 5
// speedup vs baseline: 4.3690x; 1.1666x over previous
#include <cuda_runtime.h>
#include <cuda_bf16.h>
#include <cstdint>

// ---------------- problem constants ----------------
#define B_   2
#define S_   2048
#define HID_ 2048
#define H_   16
#define QL_  1536
#define KVL_ 512
#define DN_  128
#define DR_  64
#define DV_  128
#define DQK_ 192
#define NT_  (B_*S_)        // 4096 tokens

typedef __nv_bfloat16 bf16;

// ---------------- scratch (static device globals; no alloc) ----------------
__device__ __align__(128) float g_qan[(size_t)NT_ * QL_];
__device__ __align__(128) float g_kvall[(size_t)NT_ * (KVL_ + DR_)];

__device__ __align__(128) bf16 g_xhi[(size_t)NT_ * HID_],  g_xlo[(size_t)NT_ * HID_];
__device__ __align__(128) bf16 g_qanhi[(size_t)NT_ * QL_], g_qanlo[(size_t)NT_ * QL_];
__device__ __align__(128) bf16 g_kvnhi[(size_t)NT_ * KVL_],g_kvnlo[(size_t)NT_ * KVL_];
__device__ __align__(128) bf16 g_athi[(size_t)NT_ * (H_*DV_)], g_atlo[(size_t)NT_ * (H_*DV_)];
__device__ __align__(128) bf16 g_wqahi[(size_t)QL_ * HID_],        g_wqalo[(size_t)QL_ * HID_];
__device__ __align__(128) bf16 g_wqbhi[(size_t)(H_*DQK_) * QL_],   g_wqblo[(size_t)(H_*DQK_) * QL_];
__device__ __align__(128) bf16 g_wkvahi[(size_t)(KVL_+DR_) * HID_],g_wkvalo[(size_t)(KVL_+DR_) * HID_];
__device__ __align__(128) bf16 g_wkvbhi[(size_t)(H_*256) * KVL_],  g_wkvblo[(size_t)(H_*256) * KVL_];
__device__ __align__(128) bf16 g_wohi[(size_t)HID_ * (H_*DV_)],    g_wolo[(size_t)HID_ * (H_*DV_)];

// attention operand planes, packed per head
__device__ __align__(128) bf16 g_aqhi[(size_t)NT_ * H_ * DQK_], g_aqlo[(size_t)NT_ * H_ * DQK_];
__device__ __align__(128) bf16 g_akhi[(size_t)NT_ * H_ * DQK_], g_aklo[(size_t)NT_ * H_ * DQK_];
__device__ __align__(128) bf16 g_avhi[(size_t)NT_ * H_ * DV_],  g_avlo[(size_t)NT_ * H_ * DV_];

// ================= PTX helpers (baseline compute_103 features only) =========
__device__ __forceinline__ uint32_t smem_u32(const void* p) {
    uint32_t a;
    asm("{ .reg .u64 t; cvta.to.shared.u64 t, %1; cvt.u32.u64 %0, t; }" : "=r"(a) : "l"(p));
    return a;
}
__device__ __forceinline__ void cp_async16(uint32_t dst, const void* src, int src_bytes) {
    asm volatile("cp.async.cg.shared.global [%0], [%1], 16, %2;"
                 :: "r"(dst), "l"(src), "r"(src_bytes) : "memory");
}
__device__ __forceinline__ void cp_commit() {
    asm volatile("cp.async.commit_group;" ::: "memory");
}
template <int N>
__device__ __forceinline__ void cp_wait() {
    asm volatile("cp.async.wait_group %0;" :: "n"(N) : "memory");
}
__device__ __forceinline__ void ldmx4(uint32_t* r, uint32_t addr) {
    asm volatile("ldmatrix.sync.aligned.m8n8.x4.shared.b16 {%0,%1,%2,%3}, [%4];"
                 : "=r"(r[0]), "=r"(r[1]), "=r"(r[2]), "=r"(r[3]) : "r"(addr));
}
__device__ __forceinline__ void ldmx4t(uint32_t* r, uint32_t addr) {
    asm volatile("ldmatrix.sync.aligned.m8n8.x4.trans.shared.b16 {%0,%1,%2,%3}, [%4];"
                 : "=r"(r[0]), "=r"(r[1]), "=r"(r[2]), "=r"(r[3]) : "r"(addr));
}
__device__ __forceinline__ void mma16816(float* c, const uint32_t* a, uint32_t b0, uint32_t b1) {
    asm("mma.sync.aligned.m16n8k16.row.col.f32.bf16.bf16.f32 "
        "{%0,%1,%2,%3}, {%4,%5,%6,%7}, {%8,%9}, {%0,%1,%2,%3};"
        : "+f"(c[0]), "+f"(c[1]), "+f"(c[2]), "+f"(c[3])
        : "r"(a[0]), "r"(a[1]), "r"(a[2]), "r"(a[3]), "r"(b0), "r"(b1));
}
__device__ __forceinline__ uint32_t packbf(float x, float y) {
    uint32_t r;
    asm("cvt.rn.bf16x2.f32 %0, %1, %2;" : "=r"(r) : "f"(y), "f"(x));
    return r;
}
__device__ __forceinline__ void split2(float x, float y, uint32_t& hi, uint32_t& lo) {
    float xh = __bfloat162float(__float2bfloat16(x));
    float yh = __bfloat162float(__float2bfloat16(y));
    hi = packbf(xh, yh);
    lo = packbf(x - xh, y - yh);
}

// ================= HMMA split-bf16 GEMM (multi-segment) ======================
#define GBK 32
#define ROWB 80
#define PLANE (128 * ROWB)
#define GBUF  (4 * PLANE)
#define GSMEM (2 * GBUF)

struct Seg {
    const bf16 *Ah, *Al, *Wh, *Wl;
    float* C;
    bf16 *P1, *P2, *P3, *P4;
    const float* fc;
    int N, K, ldc, gx, epi;   // epi: 0=fp32 C, 1=Q(scale+rope+split), 2=KV split
};

__device__ __forceinline__ void load_tile(
    const bf16* __restrict__ g, int ld, int rowbase, int rowlim,
    int kcol, uint32_t sdst, int tid)
{
#pragma unroll
    for (int i = 0; i < 2; ++i) {
        int idx = tid + i * 256;
        int r = idx >> 2;
        int c8 = (idx & 3) << 3;
        int gr = rowbase + r;
        int ok = (gr < rowlim);
        const bf16* src = g + (size_t)(ok ? gr : rowbase) * ld + kcol + c8;
        cp_async16(sdst + r * ROWB + c8 * 2, src, ok ? 16 : 0);
    }
}

extern __shared__ uint8_t dsm[];

__global__ __launch_bounds__(256, 2) void gemm_hmma(Seg s0, Seg s1, int nb0)
{
    const Seg s = (blockIdx.x < (unsigned)nb0) ? s0 : s1;
    const int bid = (blockIdx.x < (unsigned)nb0) ? blockIdx.x : blockIdx.x - nb0;
    const int tid  = threadIdx.x;
    const int wid  = tid >> 5;
    const int lane = tid & 31;
    const int bm = (bid / s.gx) * 128;
    const int bn = (bid % s.gx) * 128;
    const int wm = (wid & 3) * 32;
    const int wn = (wid >> 2) * 64;
    const uint32_t sb = smem_u32(dsm);

    float acc[2][8][4];
#pragma unroll
    for (int i = 0; i < 2; i++)
#pragma unroll
        for (int j = 0; j < 8; j++)
#pragma unroll
            for (int k = 0; k < 4; k++) acc[i][j][k] = 0.f;

    const int nchunks = s.K / GBK;

    {
        uint32_t buf = sb;
        load_tile(s.Ah, s.K, bm, 1 << 30, 0, buf,             tid);
        load_tile(s.Al, s.K, bm, 1 << 30, 0, buf + PLANE,     tid);
        load_tile(s.Wh, s.K, bn, s.N,     0, buf + 2 * PLANE, tid);
        load_tile(s.Wl, s.K, bn, s.N,     0, buf + 3 * PLANE, tid);
        cp_commit();
    }

    const uint32_t a_off = (uint32_t)((wm + (lane & 15)) * ROWB + ((lane >> 4) << 3) * 2);
    const uint32_t b_off = (uint32_t)((wn + (lane & 7)) * ROWB + ((lane >> 3) << 3) * 2);

    for (int c = 0; c < nchunks; ++c) {
        if (c + 1 < nchunks) {
            uint32_t buf = sb + ((c + 1) & 1) * GBUF;
            int kcol = (c + 1) * GBK;
            load_tile(s.Ah, s.K, bm, 1 << 30, kcol, buf,             tid);
            load_tile(s.Al, s.K, bm, 1 << 30, kcol, buf + PLANE,     tid);
            load_tile(s.Wh, s.K, bn, s.N,     kcol, buf + 2 * PLANE, tid);
            load_tile(s.Wl, s.K, bn, s.N,     kcol, buf + 3 * PLANE, tid);
            cp_commit();
            cp_wait<1>();
        } else {
            cp_wait<0>();
        }
        __syncthreads();

        const uint32_t buf = sb + (c & 1) * GBUF;

        uint32_t afr[2][2][2][4];
#pragma unroll
        for (int pl = 0; pl < 2; ++pl)
#pragma unroll
            for (int mi = 0; mi < 2; ++mi)
#pragma unroll
                for (int kf = 0; kf < 2; ++kf)
                    ldmx4(afr[pl][mi][kf],
                          buf + pl * PLANE + a_off + mi * 16 * ROWB + kf * 32);

#pragma unroll
        for (int ni = 0; ni < 8; ++ni) {
            uint32_t bhi[4], blo[4];
            ldmx4(bhi, buf + 2 * PLANE + b_off + ni * 8 * ROWB);
            ldmx4(blo, buf + 3 * PLANE + b_off + ni * 8 * ROWB);
#pragma unroll
            for (int mi = 0; mi < 2; ++mi) {
                float* d = acc[mi][ni];
                mma16816(d, afr[0][mi][0], bhi[0], bhi[1]);
                mma16816(d, afr[0][mi][1], bhi[2], bhi[3]);
                mma16816(d, afr[0][mi][0], blo[0], blo[1]);
                mma16816(d, afr[0][mi][1], blo[2], blo[3]);
                mma16816(d, afr[1][mi][0], bhi[0], bhi[1]);
                mma16816(d, afr[1][mi][1], bhi[2], bhi[3]);
            }
        }
        __syncthreads();
    }

    // -------- epilogues --------
    const int r0 = bm + wm + (lane >> 2);
    const int cb = bn + wn + (lane & 3) * 2;

    if (s.epi == 0) {
#pragma unroll
        for (int mi = 0; mi < 2; ++mi)
#pragma unroll
            for (int ni = 0; ni < 8; ++ni) {
                int col = cb + ni * 8;
                if (col < s.N) {
                    int row = r0 + mi * 16;
                    *reinterpret_cast<float2*>(&s.C[(size_t)row * s.ldc + col]) =
                        make_float2(acc[mi][ni][0], acc[mi][ni][1]);
                    *reinterpret_cast<float2*>(&s.C[(size_t)(row + 8) * s.ldc + col]) =
                        make_float2(acc[mi][ni][2], acc[mi][ni][3]);
                }
            }
    } else if (s.epi == 1) {
        // Q: scale + rope(d>=128) + split -> P1/P2 at [row*3072 + col]
        const float sc = 0.07216878364870323f;   // 1/sqrt(192)
#pragma unroll
        for (int mi = 0; mi < 2; ++mi)
#pragma unroll
            for (int ni = 0; ni < 8; ++ni) {
                int col = cb + ni * 8;
                int row = r0 + mi * 16;
                int d = col % 192;
                float a0 = acc[mi][ni][0], a1 = acc[mi][ni][1];
                float a2 = acc[mi][ni][2], a3 = acc[mi][ni][3];
                if (d >= 128) {
                    int p = (d - 128) >> 1;
                    int sA = row & (S_ - 1), sB = (row + 8) & (S_ - 1);
                    float cA = s.fc[(sA * 32 + p) * 2], snA = s.fc[(sA * 32 + p) * 2 + 1];
                    float cB = s.fc[(sB * 32 + p) * 2], snB = s.fc[(sB * 32 + p) * 2 + 1];
                    float t0 = a0 * cA - a1 * snA, t1 = a0 * snA + a1 * cA;
                    float t2 = a2 * cB - a3 * snB, t3 = a2 * snB + a3 * cB;
                    a0 = t0; a1 = t1; a2 = t2; a3 = t3;
                }
                a0 *= sc; a1 *= sc; a2 *= sc; a3 *= sc;
                uint32_t hh, ll;
                split2(a0, a1, hh, ll);
                *reinterpret_cast<uint32_t*>(&s.P1[(size_t)row * 3072 + col]) = hh;
                *reinterpret_cast<uint32_t*>(&s.P2[(size_t)row * 3072 + col]) = ll;
                split2(a2, a3, hh, ll);
                *reinterpret_cast<uint32_t*>(&s.P1[(size_t)(row + 8) * 3072 + col]) = hh;
                *reinterpret_cast<uint32_t*>(&s.P2[(size_t)(row + 8) * 3072 + col]) = ll;
            }
    } else {
        // KV: d<128 -> K-nope planes (stride 192), d>=128 -> V planes (stride 128)
#pragma unroll
        for (int mi = 0; mi < 2; ++mi)
#pragma unroll
            for (int ni = 0; ni < 8; ++ni) {
                int col = cb + ni * 8;
                int row = r0 + mi * 16;
                int h = col >> 8, d = col & 255;
                bf16 *H, *L;
                size_t idx; size_t st;
                if (d < 128) { idx = ((size_t)row * 16 + h) * 192 + d;        st = (size_t)8 * 16 * 192; H = s.P1; L = s.P2; }
                else         { idx = ((size_t)row * 16 + h) * 128 + (d - 128); st = (size_t)8 * 16 * 128; H = s.P3; L = s.P4; }
                uint32_t hh, ll;
                split2(acc[mi][ni][0], acc[mi][ni][1], hh, ll);
                *reinterpret_cast<uint32_t*>(&H[idx]) = hh;
                *reinterpret_cast<uint32_t*>(&L[idx]) = ll;
                split2(acc[mi][ni][2], acc[mi][ni][3], hh, ll);
                *reinterpret_cast<uint32_t*>(&H[idx + st]) = hh;
                *reinterpret_cast<uint32_t*>(&L[idx + st]) = ll;
            }
    }
}

// ================= converts (single merged launch) =================
struct CTab {
    const float* s[6];
    bf16 *h[6], *l[6];
    unsigned n4[6];
    unsigned start[7];
};

__global__ void convert_all(CTab t)
{
    unsigned b = blockIdx.x;
    int k = 0;
#pragma unroll
    for (int j = 1; j < 6; j++) if (b >= t.start[j]) k = j;
    size_t i = (size_t)(b - t.start[k]) * 256 + threadIdx.x;
    if (i >= t.n4[k]) return;
    float4 v = reinterpret_cast<const float4*>(t.s[k])[i];
    bf16 h0 = __float2bfloat16(v.x), h1 = __float2bfloat16(v.y);
    bf16 h2 = __float2bfloat16(v.z), h3 = __float2bfloat16(v.w);
    bf16 l0 = __float2bfloat16(v.x - __bfloat162float(h0));
    bf16 l1 = __float2bfloat16(v.y - __bfloat162float(h1));
    bf16 l2 = __float2bfloat16(v.z - __bfloat162float(h2));
    bf16 l3 = __float2bfloat16(v.w - __bfloat162float(h3));
    __nv_bfloat162* hp = reinterpret_cast<__nv_bfloat162*>(t.h[k]);
    __nv_bfloat162* lp = reinterpret_cast<__nv_bfloat162*>(t.l[k]);
    hp[2*i]   = __nv_bfloat162(h0, h1); hp[2*i+1] = __nv_bfloat162(h2, h3);
    lp[2*i]   = __nv_bfloat162(l0, l1); lp[2*i+1] = __nv_bfloat162(l2, l3);
}

// ---------------- RMSNorm fused with split-convert ----------------
__global__ void rmsnorm_split(const float* __restrict__ x, const float* __restrict__ w,
                              bf16* __restrict__ hi, bf16* __restrict__ lo,
                              int n, int instride)
{
    const int row = blockIdx.x;
    const float* p = x + (size_t)row * instride;
    __shared__ float red[256];
    float sacc = 0.f;
    for (int i = threadIdx.x; i < n; i += 256) { float v = p[i]; sacc += v * v; }
    red[threadIdx.x] = sacc;
    __syncthreads();
    for (int o = 128; o > 0; o >>= 1) {
        if (threadIdx.x < o) red[threadIdx.x] += red[threadIdx.x + o];
        __syncthreads();
    }
    float inv = rsqrtf(red[0] / n + 1e-6f);
    for (int i = threadIdx.x * 2; i < n; i += 512) {
        float v0 = p[i] * inv * w[i];
        float v1 = p[i + 1] * inv * w[i + 1];
        uint32_t hh, ll;
        split2(v0, v1, hh, ll);
        *reinterpret_cast<uint32_t*>(&hi[(size_t)row * n + i]) = hh;
        *reinterpret_cast<uint32_t*>(&lo[(size_t)row * n + i]) = ll;
    }
}

// ---------------- k_pe: rope + split + broadcast to 16 heads ----------------
__global__ void kpe_rope_bcast(const float* __restrict__ kvall, const float* __restrict__ fc,
                               bf16* __restrict__ akhi, bf16* __restrict__ aklo)
{
    int idx = blockIdx.x * blockDim.x + threadIdx.x;
    if (idx >= NT_ * 32) return;
    int t = idx >> 5, p = idx & 31;
    int sfx = t & (S_ - 1);
    float xr = kvall[(size_t)t * (KVL_ + DR_) + KVL_ + 2 * p];
    float xi = kvall[(size_t)t * (KVL_ + DR_) + KVL_ + 2 * p + 1];
    float c = fc[(sfx * 32 + p) * 2], sn = fc[(sfx * 32 + p) * 2 + 1];
    float r0 = xr * c - xi * sn, r1 = xr * sn + xi * c;
    uint32_t hh, ll;
    split2(r0, r1, hh, ll);
    size_t base = ((size_t)t * 16) * 192 + 128 + 2 * p;
#pragma unroll
    for (int h = 0; h < 16; h++) {
        *reinterpret_cast<uint32_t*>(&akhi[base + h * 192]) = hh;
        *reinterpret_cast<uint32_t*>(&aklo[base + h * 192]) = ll;
    }
}

// ================= HMMA flash attention =====================================
#define AQP 200
#define AVP 136
#define SM_QLO 12800
#define SM_ST  25600
#define STG_EL 43008
#define ATT_SMEM ((SM_ST + 2 * STG_EL) * 2)   // 223232 bytes

__global__ __launch_bounds__(128, 1) void attn_hmma(
    const bf16* __restrict__ qhi, const bf16* __restrict__ qlo,
    const bf16* __restrict__ khi, const bf16* __restrict__ klo,
    const bf16* __restrict__ vhi, const bf16* __restrict__ vlo,
    bf16* __restrict__ ohi, bf16* __restrict__ olo)
{
    extern __shared__ bf16 asmem[];
    const int qt = gridDim.x - 1 - blockIdx.x;    // long CTAs first
    const int h = blockIdx.y, b = blockIdx.z;
    const int tid = threadIdx.x, wid = tid >> 5, lane = tid & 31;
    const int q0 = qt * 64;
    const uint32_t sb = smem_u32(asmem);

    for (int i = tid; i < 1536; i += 128) {
        int r = i / 24, c = (i % 24) * 8;
        size_t g = ((size_t)(b * S_ + q0 + r) * H_ + h) * 192 + c;
        uint32_t d = sb + (r * AQP + c) * 2;
        cp_async16(d, qhi + g, 16);
        cp_async16(d + SM_QLO * 2, qlo + g, 16);
    }
    cp_commit();

    auto load_kv = [&](int kt, int s) {
        const int k0 = kt * 64;
        const uint32_t st = sb + (SM_ST + s * STG_EL) * 2;
        for (int i = tid; i < 1536; i += 128) {
            int r = i / 24, c = (i % 24) * 8;
            size_t g = ((size_t)(b * S_ + k0 + r) * H_ + h) * 192 + c;
            uint32_t d = st + (r * AQP + c) * 2;
            cp_async16(d, khi + g, 16);
            cp_async16(d + 12800 * 2, klo + g, 16);
        }
        for (int i = tid; i < 1024; i += 128) {
            int r = i / 16, c = (i % 16) * 8;
            size_t g = ((size_t)(b * S_ + k0 + r) * H_ + h) * 128 + c;
            uint32_t d = st + 25600 * 2 + (r * AVP + c) * 2;
            cp_async16(d, vhi + g, 16);
            cp_async16(d + 8704 * 2, vlo + g, 16);
        }
        cp_commit();
    };

    float oa[16][4];
#pragma unroll
    for (int j = 0; j < 16; j++)
#pragma unroll
        for (int e = 0; e < 4; e++) oa[j][e] = 0.f;
    float m0 = -1e30f, m1 = -1e30f, l0 = 0.f, l1 = 0.f;

    const int ntiles = qt + 1;
    load_kv(0, 0);

    const uint32_t qoff = sb + ((wid * 16 + (lane & 15)) * AQP + (lane >> 4) * 8) * 2;

    for (int kt = 0; kt < ntiles; kt++) {
        if (kt + 1 < ntiles) { load_kv(kt + 1, (kt + 1) & 1); cp_wait<1>(); }
        else                 { cp_wait<0>(); }
        __syncthreads();
        const uint32_t st = sb + (SM_ST + (kt & 1) * STG_EL) * 2;

        float c[8][4];
#pragma unroll
        for (int j = 0; j < 8; j++)
#pragma unroll
            for (int e = 0; e < 4; e++) c[j][e] = 0.f;

        const uint32_t kb = st + ((lane & 7) * AQP + (lane >> 3) * 8) * 2;
#pragma unroll
        for (int kp = 0; kp < 6; kp++) {
            uint32_t qh[2][4], ql[2][4];
            ldmx4(qh[0], qoff + kp * 64);
            ldmx4(qh[1], qoff + kp * 64 + 32);
            ldmx4(ql[0], qoff + SM_QLO * 2 + kp * 64);
            ldmx4(ql[1], qoff + SM_QLO * 2 + kp * 64 + 32);
#pragma unroll
            for (int nb = 0; nb < 8; nb++) {
                uint32_t kh[4], kl[4];
                ldmx4(kh, kb + nb * 8 * AQP * 2 + kp * 64);
                ldmx4(kl, kb + 12800 * 2 + nb * 8 * AQP * 2 + kp * 64);
                mma16816(c[nb], qh[0], kh[0], kh[1]);
                mma16816(c[nb], qh[1], kh[2], kh[3]);
                mma16816(c[nb], qh[0], kl[0], kl[1]);
                mma16816(c[nb], qh[1], kl[2], kl[3]);
                mma16816(c[nb], ql[0], kh[0], kh[1]);
                mma16816(c[nb], ql[1], kh[2], kh[3]);
            }
        }

        if (kt == qt) {
            const int r0 = wid * 16 + (lane >> 2);
            const int cbase = (lane & 3) * 2;
#pragma unroll
            for (int nb = 0; nb < 8; nb++) {
                int col = nb * 8 + cbase;
                if (col     > r0    ) c[nb][0] = -1e30f;
                if (col + 1 > r0    ) c[nb][1] = -1e30f;
                if (col     > r0 + 8) c[nb][2] = -1e30f;
                if (col + 1 > r0 + 8) c[nb][3] = -1e30f;
            }
        }

        float mx0 = -1e30f, mx1 = -1e30f;
#pragma unroll
        for (int nb = 0; nb < 8; nb++) {
            mx0 = fmaxf(mx0, fmaxf(c[nb][0], c[nb][1]));
            mx1 = fmaxf(mx1, fmaxf(c[nb][2], c[nb][3]));
        }
        mx0 = fmaxf(mx0, __shfl_xor_sync(0xffffffffu, mx0, 1));
        mx0 = fmaxf(mx0, __shfl_xor_sync(0xffffffffu, mx0, 2));
        mx1 = fmaxf(mx1, __shfl_xor_sync(0xffffffffu, mx1, 1));
        mx1 = fmaxf(mx1, __shfl_xor_sync(0xffffffffu, mx1, 2));
        float mn0 = fmaxf(m0, mx0), mn1 = fmaxf(m1, mx1);
        float co0 = __expf(m0 - mn0), co1 = __expf(m1 - mn1);
        m0 = mn0; m1 = mn1;
        float s0 = 0.f, s1 = 0.f;
#pragma unroll
        for (int nb = 0; nb < 8; nb++) {
            c[nb][0] = __expf(c[nb][0] - mn0); s0 += c[nb][0];
            c[nb][1] = __expf(c[nb][1] - mn0); s0 += c[nb][1];
            c[nb][2] = __expf(c[nb][2] - mn1); s1 += c[nb][2];
            c[nb][3] = __expf(c[nb][3] - mn1); s1 += c[nb][3];
        }
        s0 += __shfl_xor_sync(0xffffffffu, s0, 1);
        s0 += __shfl_xor_sync(0xffffffffu, s0, 2);
        s1 += __shfl_xor_sync(0xffffffffu, s1, 1);
        s1 += __shfl_xor_sync(0xffffffffu, s1, 2);
        l0 = l0 * co0 + s0;
        l1 = l1 * co1 + s1;
#pragma unroll
        for (int j = 0; j < 16; j++) {
            oa[j][0] *= co0; oa[j][1] *= co0;
            oa[j][2] *= co1; oa[j][3] *= co1;
        }

        const uint32_t vb = st + 25600 * 2 + ((lane & 15) * AVP + (lane >> 4) * 8) * 2;
#pragma unroll
        for (int kk = 0; kk < 4; kk++) {
            uint32_t ah[4], al[4];
            split2(c[2*kk][0],   c[2*kk][1],   ah[0], al[0]);
            split2(c[2*kk][2],   c[2*kk][3],   ah[1], al[1]);
            split2(c[2*kk+1][0], c[2*kk+1][1], ah[2], al[2]);
            split2(c[2*kk+1][2], c[2*kk+1][3], ah[3], al[3]);
#pragma unroll
            for (int n16 = 0; n16 < 8; n16++) {
                uint32_t vh[4], vl[4];
                ldmx4t(vh, vb + (kk * 16 * AVP + n16 * 16) * 2);
                ldmx4t(vl, vb + 8704 * 2 + (kk * 16 * AVP + n16 * 16) * 2);
                float* o0 = oa[2 * n16];
                float* o1 = oa[2 * n16 + 1];
                mma16816(o0, ah, vh[0], vh[1]);
                mma16816(o1, ah, vh[2], vh[3]);
                mma16816(o0, al, vh[0], vh[1]);
                mma16816(o1, al, vh[2], vh[3]);
                mma16816(o0, ah, vl[0], vl[1]);
                mma16816(o1, ah, vl[2], vl[3]);
            }
        }
        __syncthreads();
    }

    // ---- finalize: split directly into bf16 hi/lo planes ----
    const float i0 = 1.f / l0, i1 = 1.f / l1;
    const int r0 = q0 + wid * 16 + (lane >> 2);
    const size_t t0 = (size_t)(b * S_ + r0);
#pragma unroll
    for (int j = 0; j < 16; j++) {
        int col = h * 128 + j * 8 + (lane & 3) * 2;
        uint32_t hh, ll;
        split2(oa[j][0] * i0, oa[j][1] * i0, hh, ll);
        *reinterpret_cast<uint32_t*>(&ohi[t0 * (H_*DV_) + col]) = hh;
        *reinterpret_cast<uint32_t*>(&olo[t0 * (H_*DV_) + col]) = ll;
        split2(oa[j][2] * i1, oa[j][3] * i1, hh, ll);
        *reinterpret_cast<uint32_t*>(&ohi[(t0 + 8) * (H_*DV_) + col]) = hh;
        *reinterpret_cast<uint32_t*>(&olo[(t0 + 8) * (H_*DV_) + col]) = ll;
    }
}

// ---------------- launcher ----------------
extern "C" void kernel_launch(void* const* d_in, const int* in_sizes, int n_in,
                              void* d_out, int out_size)
{
    const float* x      = (const float*)d_in[0];
    const float* freqs  = (const float*)d_in[1];
    const float* wq_a   = (const float*)d_in[2];
    const float* q_an_w = (const float*)d_in[3];
    const float* wq_b   = (const float*)d_in[4];
    const float* wkv_a  = (const float*)d_in[5];
    const float* kv_n_w = (const float*)d_in[6];
    const float* wkv_b  = (const float*)d_in[7];
    const float* wo     = (const float*)d_in[8];
    float* out = (float*)d_out;

    float *qan, *kvall;
    cudaGetSymbolAddress((void**)&qan,   g_qan);
    cudaGetSymbolAddress((void**)&kvall, g_kvall);

    bf16 *xhi,*xlo,*qanhi,*qanlo,*kvnhi,*kvnlo,*athi,*atlo;
    bf16 *wqahi,*wqalo,*wqbhi,*wqblo,*wkvahi,*wkvalo,*wkvbhi,*wkvblo,*wohi,*wolo;
    bf16 *aqhi,*aqlo,*akhi,*aklo,*avhi,*avlo;
    cudaGetSymbolAddress((void**)&xhi, g_xhi);     cudaGetSymbolAddress((void**)&xlo, g_xlo);
    cudaGetSymbolAddress((void**)&qanhi, g_qanhi); cudaGetSymbolAddress((void**)&qanlo, g_qanlo);
    cudaGetSymbolAddress((void**)&kvnhi, g_kvnhi); cudaGetSymbolAddress((void**)&kvnlo, g_kvnlo);
    cudaGetSymbolAddress((void**)&athi, g_athi);   cudaGetSymbolAddress((void**)&atlo, g_atlo);
    cudaGetSymbolAddress((void**)&wqahi, g_wqahi); cudaGetSymbolAddress((void**)&wqalo, g_wqalo);
    cudaGetSymbolAddress((void**)&wqbhi, g_wqbhi); cudaGetSymbolAddress((void**)&wqblo, g_wqblo);
    cudaGetSymbolAddress((void**)&wkvahi, g_wkvahi); cudaGetSymbolAddress((void**)&wkvalo, g_wkvalo);
    cudaGetSymbolAddress((void**)&wkvbhi, g_wkvbhi); cudaGetSymbolAddress((void**)&wkvblo, g_wkvblo);
    cudaGetSymbolAddress((void**)&wohi, g_wohi);   cudaGetSymbolAddress((void**)&wolo, g_wolo);
    cudaGetSymbolAddress((void**)&aqhi, g_aqhi);   cudaGetSymbolAddress((void**)&aqlo, g_aqlo);
    cudaGetSymbolAddress((void**)&akhi, g_akhi);   cudaGetSymbolAddress((void**)&aklo, g_aklo);
    cudaGetSymbolAddress((void**)&avhi, g_avhi);   cudaGetSymbolAddress((void**)&avlo, g_avlo);

    cudaFuncSetAttribute(gemm_hmma, cudaFuncAttributeMaxDynamicSharedMemorySize, GSMEM);
    cudaFuncSetAttribute(attn_hmma, cudaFuncAttributeMaxDynamicSharedMemorySize, ATT_SMEM);

    // ---- merged input/weight converts ----
    CTab ct;
    const float* srcs[6] = {x, wq_a, wq_b, wkv_a, wkv_b, wo};
    bf16* his[6] = {xhi, wqahi, wqbhi, wkvahi, wkvbhi, wohi};
    bf16* los[6] = {xlo, wqalo, wqblo, wkvalo, wkvblo, wolo};
    size_t ns[6] = {(size_t)NT_*HID_, (size_t)QL_*HID_, (size_t)(H_*DQK_)*QL_,
                    (size_t)(KVL_+DR_)*HID_, (size_t)(H_*256)*KVL_, (size_t)HID_*(H_*DV_)};
    unsigned cum = 0;
    for (int i = 0; i < 6; i++) {
        ct.s[i] = srcs[i]; ct.h[i] = his[i]; ct.l[i] = los[i];
        ct.n4[i] = (unsigned)(ns[i] / 4);
        ct.start[i] = cum;
        cum += (ct.n4[i] + 255) / 256;
    }
    ct.start[6] = cum;
    convert_all<<<cum, 256>>>(ct);

    // ---- L1: wq_a + wkv_a (both read x planes) ----
    {
        Seg a = {xhi, xlo, wqahi, wqalo, qan, nullptr, nullptr, nullptr, nullptr,
                 freqs, QL_, HID_, QL_, QL_/128, 0};
        Seg b = {xhi, xlo, wkvahi, wkvalo, kvall, nullptr, nullptr, nullptr, nullptr,
                 freqs, KVL_+DR_, HID_, KVL_+DR_, (KVL_+DR_+127)/128, 0};
        int nb0 = (QL_/128) * (NT_/128);
        int nb1 = ((KVL_+DR_+127)/128) * (NT_/128);
        gemm_hmma<<<nb0 + nb1, 256, GSMEM>>>(a, b, nb0);
    }

    // ---- rmsnorms fused with split ----
    rmsnorm_split<<<NT_, 256>>>(qan, q_an_w, qanhi, qanlo, QL_, QL_);
    rmsnorm_split<<<NT_, 256>>>(kvall, kv_n_w, kvnhi, kvnlo, KVL_, KVL_ + DR_);

    // ---- L2: wq_b (epi Q: scale+rope+split) + wkv_b (epi KV split) ----
    {
        Seg a = {qanhi, qanlo, wqbhi, wqblo, nullptr, aqhi, aqlo, nullptr, nullptr,
                 freqs, H_*DQK_, QL_, 0, (H_*DQK_)/128, 1};
        Seg b = {kvnhi, kvnlo, wkvbhi, wkvblo, nullptr, akhi, aklo, avhi, avlo,
                 freqs, H_*256, KVL_, 0, (H_*256)/128, 2};
        int nb0 = ((H_*DQK_)/128) * (NT_/128);
        int nb1 = ((H_*256)/128) * (NT_/128);
        gemm_hmma<<<nb0 + nb1, 256, GSMEM>>>(a, b, nb0);
    }

    // ---- k_pe rope + broadcast into K planes ----
    kpe_rope_bcast<<<(NT_ * 32 + 255) / 256, 256>>>(kvall, freqs, akhi, aklo);

    // ---- attention (writes split planes directly) ----
    attn_hmma<<<dim3(S_ / 64, H_, B_), 128, ATT_SMEM>>>(
        aqhi, aqlo, akhi, aklo, avhi, avlo, athi, atlo);

    // ---- L3: wo ----
    {
        Seg a = {athi, atlo, wohi, wolo, out, nullptr, nullptr, nullptr, nullptr,
                 freqs, HID_, H_*DV_, HID_, HID_/128, 0};
        int nb0 = (HID_/128) * (NT_/128);
        gemm_hmma<<<nb0, 256, GSMEM>>>(a, a, nb0);
    }
}